// round 3
// baseline (speedup 1.0000x reference)
#include <cuda_runtime.h>
#include <cuda_bf16.h>

#define HIDDEN 256
#define NNODES 20000
#define NEDGES 320000

// Scratch (device globals: allocation-free rule). 16B-aligned for float4 access.
__device__ __align__(16) float g_h1[NNODES * HIDDEN];        // prelu->enc->masked x
__device__ __align__(16) float g_aggr[NNODES * HIDDEN];      // segment-sum result
__device__ __align__(16) float g_h2[NNODES * 2 * HIDDEN];    // hidden after W1+relu
__device__ int g_is64;                                       // index dtype flag

// Probe: int64 nonneg values < 2^31 have zero high words; int32 node ids at odd
// word positions are ~never all zero across 32 samples.
__global__ void detect_idx_dtype(const int* __restrict__ ei_words)
{
    int is64 = 1;
    for (int i = 1; i < 64; i += 2)
        if (ei_words[i] != 0) { is64 = 0; break; }
    g_is64 = is64;
}

__device__ __forceinline__ long long load_idx(const void* p, long long i, int is64)
{
    return is64 ? ((const long long*)p)[i] : (long long)((const int*)p)[i];
}

__device__ __forceinline__ void red4(float4* addr, float4 v) {
    asm volatile("red.global.add.v4.f32 [%0], {%1, %2, %3, %4};"
                 :: "l"(addr), "f"(v.x), "f"(v.y), "f"(v.z), "f"(v.w)
                 : "memory");
}

// ---------------------------------------------------------------------------
// Tiled fp32 GEMM:  C[M,N] = op(A[M,K] @ W[N,K]^T (+ bias))
// MODE 0: A gets PReLU on load, no bias       (enc_to_dec)
// MODE 1: + bias, ReLU epilogue               (GIN layer 1)
// MODE 2: + bias                              (GIN layer 2)
// BM=128, BN=64, BK=16, 256 threads, 8x4 micro-tile per thread.
// ---------------------------------------------------------------------------
template <int MODE>
__global__ __launch_bounds__(256)
void sgemm128x64(const float* __restrict__ A, const float* __restrict__ W,
                 const float* __restrict__ bias, float* __restrict__ C,
                 int M, int N, int K, const float* __restrict__ prelu_pa)
{
    constexpr int BM = 128, BN = 64, BK = 16;
    __shared__ __align__(16) float As[BK][BM];
    __shared__ __align__(16) float Bs[BK][BN];

    const int tid = threadIdx.x;
    const int tx = tid & 15;    // 16 col-groups of 4
    const int ty = tid >> 4;    // 16 row-groups of 8
    const int m0 = blockIdx.y * BM;
    const int n0 = blockIdx.x * BN;

    float pa = 0.f;
    if (MODE == 0) pa = *prelu_pa;

    float acc[8][4];
#pragma unroll
    for (int i = 0; i < 8; i++)
#pragma unroll
        for (int j = 0; j < 4; j++) acc[i][j] = 0.f;

    for (int k0 = 0; k0 < K; k0 += BK) {
        // Load A tile (BM x BK) -> As[k][m], transposed, PReLU fused for MODE 0
#pragma unroll
        for (int q = tid; q < BM * BK / 4; q += 256) {
            int r  = q >> 2;     // 0..127
            int k4 = q & 3;      // 0..3 (float4 along K)
            int row = m0 + r;
            float4 v = make_float4(0.f, 0.f, 0.f, 0.f);
            if (row < M)
                v = *(const float4*)(A + (long long)row * K + k0 + k4 * 4);
            if (MODE == 0) {
                v.x = v.x >= 0.f ? v.x : pa * v.x;
                v.y = v.y >= 0.f ? v.y : pa * v.y;
                v.z = v.z >= 0.f ? v.z : pa * v.z;
                v.w = v.w >= 0.f ? v.w : pa * v.w;
            }
            As[k4 * 4 + 0][r] = v.x;
            As[k4 * 4 + 1][r] = v.y;
            As[k4 * 4 + 2][r] = v.z;
            As[k4 * 4 + 3][r] = v.w;
        }
        // Load W tile (BN rows x BK cols of W[N,K]) -> Bs[k][n]
        {
            int n  = tid >> 2;   // 0..63
            int k4 = tid & 3;
            float4 v = *(const float4*)(W + (long long)(n0 + n) * K + k0 + k4 * 4);
            Bs[k4 * 4 + 0][n] = v.x;
            Bs[k4 * 4 + 1][n] = v.y;
            Bs[k4 * 4 + 2][n] = v.z;
            Bs[k4 * 4 + 3][n] = v.w;
        }
        __syncthreads();

#pragma unroll
        for (int k = 0; k < BK; k++) {
            float4 a0 = *(const float4*)&As[k][ty * 8];
            float4 a1 = *(const float4*)&As[k][ty * 8 + 4];
            float4 b4 = *(const float4*)&Bs[k][tx * 4];
            float a[8] = {a0.x, a0.y, a0.z, a0.w, a1.x, a1.y, a1.z, a1.w};
            float b[4] = {b4.x, b4.y, b4.z, b4.w};
#pragma unroll
            for (int i = 0; i < 8; i++)
#pragma unroll
                for (int j = 0; j < 4; j++)
                    acc[i][j] = fmaf(a[i], b[j], acc[i][j]);
        }
        __syncthreads();
    }

    float bv[4] = {0.f, 0.f, 0.f, 0.f};
    if (MODE >= 1) {
        float4 b4 = *(const float4*)(bias + n0 + tx * 4);
        bv[0] = b4.x; bv[1] = b4.y; bv[2] = b4.z; bv[3] = b4.w;
    }
#pragma unroll
    for (int i = 0; i < 8; i++) {
        int row = m0 + ty * 8 + i;
        if (row >= M) continue;
        float4 o = make_float4(acc[i][0], acc[i][1], acc[i][2], acc[i][3]);
        if (MODE >= 1) { o.x += bv[0]; o.y += bv[1]; o.z += bv[2]; o.w += bv[3]; }
        if (MODE == 1) {
            o.x = fmaxf(o.x, 0.f); o.y = fmaxf(o.y, 0.f);
            o.z = fmaxf(o.z, 0.f); o.w = fmaxf(o.w, 0.f);
        }
        *(float4*)(C + (long long)row * N + n0 + tx * 4) = o;
    }
}

// Zero the masked rows of h1 (duplicates are idempotent). One block per index.
__global__ void mask_zero(float* __restrict__ h, const void* __restrict__ idx)
{
    long long r = load_idx(idx, blockIdx.x, g_is64);
    ((float4*)(h + r * HIDDEN))[threadIdx.x] = make_float4(0.f, 0.f, 0.f, 0.f);
}

// aggr[i] = h1[i] + E1[4] + E2[0]   (self-loop term; also serves as init)
__global__ __launch_bounds__(256)
void init_aggr(const float* __restrict__ h1, const float* __restrict__ E1,
               const float* __restrict__ E2, float* __restrict__ aggr)
{
    int idx = blockIdx.x * blockDim.x + threadIdx.x;    // over NNODES*64 float4
    if (idx >= NNODES * (HIDDEN / 4)) return;
    int c = idx & 63;
    float4 a  = ((const float4*)h1)[idx];
    float4 e1 = ((const float4*)(E1 + 4 * HIDDEN))[c];
    float4 e2 = ((const float4*)E2)[c];
    ((float4*)aggr)[idx] = make_float4(a.x + e1.x + e2.x, a.y + e1.y + e2.y,
                                       a.z + e1.z + e2.z, a.w + e1.w + e2.w);
}

// One warp per edge: aggr[dst] += x[src] + E1[a0] + E2[a1]  via vector red.
__global__ __launch_bounds__(256)
void edge_scatter(const float* __restrict__ x, const void* __restrict__ ei,
                  const void* __restrict__ ea, const float* __restrict__ E1,
                  const float* __restrict__ E2, float* __restrict__ aggr)
{
    int e = blockIdx.x * 8 + (threadIdx.x >> 5);
    if (e >= NEDGES) return;
    const int is64 = g_is64;
    int lane = threadIdx.x & 31;
    int src = (int)load_idx(ei, e, is64);
    int dst = (int)load_idx(ei, (long long)NEDGES + e, is64);
    int a0  = (int)load_idx(ea, 2LL * e, is64);
    int a1  = (int)load_idx(ea, 2LL * e + 1, is64);
    const float4* xs = (const float4*)(x + (long long)src * HIDDEN);
    const float4* p1 = (const float4*)(E1 + a0 * HIDDEN);
    const float4* p2 = (const float4*)(E2 + a1 * HIDDEN);
    float4* out = (float4*)(aggr + (long long)dst * HIDDEN);
#pragma unroll
    for (int i = 0; i < 2; i++) {
        int c = lane + 32 * i;
        float4 xv = xs[c], v1 = p1[c], v2 = p2[c];
        float4 m = make_float4(xv.x + v1.x + v2.x, xv.y + v1.y + v2.y,
                               xv.z + v1.z + v2.z, xv.w + v1.w + v2.w);
        red4(out + c, m);
    }
}

extern "C" void kernel_launch(void* const* d_in, const int* in_sizes, int n_in,
                              void* d_out, int out_size)
{
    const float* x     = (const float*)d_in[0];
    const void*  ei    = d_in[1];
    const void*  ea    = d_in[2];
    const void*  mask  = d_in[3];
    const float* pa    = (const float*)d_in[4];
    const float* W_enc = (const float*)d_in[5];
    const float* E1    = (const float*)d_in[6];
    const float* E2    = (const float*)d_in[7];
    const float* W1    = (const float*)d_in[8];
    const float* b1    = (const float*)d_in[9];
    const float* W2    = (const float*)d_in[10];
    const float* b2    = (const float*)d_in[11];
    float* out = (float*)d_out;

    float *h1, *aggr, *h2;
    cudaGetSymbolAddress((void**)&h1,   g_h1);
    cudaGetSymbolAddress((void**)&aggr, g_aggr);
    cudaGetSymbolAddress((void**)&h2,   g_h2);

    const int MB = (NNODES + 127) / 128;   // 157

    // 0) detect int32 vs int64 index dtype
    detect_idx_dtype<<<1, 1>>>((const int*)ei);

    // 1) h1 = prelu(x) @ W_enc^T
    sgemm128x64<0><<<dim3(HIDDEN / 64, MB), 256>>>(
        x, W_enc, nullptr, h1, NNODES, HIDDEN, HIDDEN, pa);

    // 2) zero masked rows
    mask_zero<<<2000, 64>>>(h1, mask);

    // 3) aggr = h1 + E1[4] + E2[0]  (self loops)
    init_aggr<<<(NNODES * (HIDDEN / 4) + 255) / 256, 256>>>(h1, E1, E2, aggr);

    // 4) aggr[dst] += h1[src] + E1[a0] + E2[a1]
    edge_scatter<<<(NEDGES + 7) / 8, 256>>>(h1, ei, ea, E1, E2, aggr);

    // 5) h2 = relu(aggr @ W1^T + b1)
    sgemm128x64<1><<<dim3(2 * HIDDEN / 64, MB), 256>>>(
        aggr, W1, b1, h2, NNODES, 2 * HIDDEN, HIDDEN, nullptr);

    // 6) out = h2 @ W2^T + b2
    sgemm128x64<2><<<dim3(HIDDEN / 64, MB), 256>>>(
        h2, W2, b2, out, NNODES, HIDDEN, 2 * HIDDEN, nullptr);
}

// round 4
// speedup vs baseline: 1.0609x; 1.0609x over previous
#include <cuda_runtime.h>
#include <cuda_bf16.h>

#define HIDDEN 256
#define NNODES 20000
#define NEDGES 320000

typedef unsigned long long u64;

// Scratch (device globals: allocation-free rule). 16B-aligned for float4 access.
__device__ __align__(16) float g_h1[NNODES * HIDDEN];        // prelu->enc->masked x
__device__ __align__(16) float g_aggr[NNODES * HIDDEN];      // segment-sum result
__device__ __align__(16) float g_h2[NNODES * 2 * HIDDEN];    // hidden after W1+relu
__device__ int g_is64;                                       // index dtype flag

// Probe: int64 nonneg values < 2^31 have zero high words; int32 node ids at odd
// word positions are ~never all zero across 32 samples.
__global__ void detect_idx_dtype(const int* __restrict__ ei_words)
{
    int is64 = 1;
    for (int i = 1; i < 64; i += 2)
        if (ei_words[i] != 0) { is64 = 0; break; }
    g_is64 = is64;
}

__device__ __forceinline__ long long load_idx(const void* p, long long i, int is64)
{
    return is64 ? ((const long long*)p)[i] : (long long)((const int*)p)[i];
}

__device__ __forceinline__ void red4(float4* addr, float4 v) {
    asm volatile("red.global.add.v4.f32 [%0], {%1, %2, %3, %4};"
                 :: "l"(addr), "f"(v.x), "f"(v.y), "f"(v.z), "f"(v.w)
                 : "memory");
}

// ---- packed f32x2 helpers (FFMA2: only reachable via PTX) ----
__device__ __forceinline__ u64 pack2(float lo, float hi) {
    u64 r; asm("mov.b64 %0, {%1, %2};" : "=l"(r) : "f"(lo), "f"(hi)); return r;
}
__device__ __forceinline__ void unpack2(u64 v, float& lo, float& hi) {
    asm("mov.b64 {%0, %1}, %2;" : "=f"(lo), "=f"(hi) : "l"(v));
}
__device__ __forceinline__ u64 ffma2(u64 a, u64 b, u64 c) {
    u64 d; asm("fma.rn.f32x2 %0, %1, %2, %3;" : "=l"(d) : "l"(a), "l"(b), "l"(c));
    return d;
}

// ---------------------------------------------------------------------------
// Tiled fp32 GEMM with packed f32x2 FMA:  C[M,N] = op(A[M,K] @ W[N,K]^T (+b))
// MODE 0: A gets PReLU on load, no bias       (enc_to_dec)
// MODE 1: + bias, ReLU epilogue               (GIN layer 1)
// MODE 2: + bias                              (GIN layer 2)
// BM=128, BN=64, BK=16, 256 threads; 8(M)x4(N) per thread, M packed in pairs.
// ---------------------------------------------------------------------------
template <int MODE>
__global__ __launch_bounds__(256)
void sgemm128x64(const float* __restrict__ A, const float* __restrict__ W,
                 const float* __restrict__ bias, float* __restrict__ C,
                 int M, int N, int K, const float* __restrict__ prelu_pa)
{
    constexpr int BM = 128, BN = 64, BK = 16;
    __shared__ __align__(16) float As[BK][BM];
    __shared__ __align__(16) float Bs[BK][BN];

    const int tid = threadIdx.x;
    const int tx = tid & 15;    // 16 col-groups of 4
    const int ty = tid >> 4;    // 16 row-groups of 8
    const int m0 = blockIdx.y * BM;
    const int n0 = blockIdx.x * BN;

    float pa = 0.f;
    if (MODE == 0) pa = *prelu_pa;

    // acc[p][j]: packed pair (rows ty*8+2p, ty*8+2p+1) x col (tx*4+j)
    u64 acc[4][4];
    const u64 zz = pack2(0.f, 0.f);
#pragma unroll
    for (int p = 0; p < 4; p++)
#pragma unroll
        for (int j = 0; j < 4; j++) acc[p][j] = zz;

    for (int k0 = 0; k0 < K; k0 += BK) {
        // Load A tile (BM x BK) -> As[k][m], transposed, PReLU fused for MODE 0
#pragma unroll
        for (int q = tid; q < BM * BK / 4; q += 256) {
            int r  = q >> 2;     // 0..127
            int k4 = q & 3;      // 0..3 (float4 along K)
            int row = m0 + r;
            float4 v = make_float4(0.f, 0.f, 0.f, 0.f);
            if (row < M)
                v = *(const float4*)(A + (long long)row * K + k0 + k4 * 4);
            if (MODE == 0) {
                v.x = v.x >= 0.f ? v.x : pa * v.x;
                v.y = v.y >= 0.f ? v.y : pa * v.y;
                v.z = v.z >= 0.f ? v.z : pa * v.z;
                v.w = v.w >= 0.f ? v.w : pa * v.w;
            }
            As[k4 * 4 + 0][r] = v.x;
            As[k4 * 4 + 1][r] = v.y;
            As[k4 * 4 + 2][r] = v.z;
            As[k4 * 4 + 3][r] = v.w;
        }
        // Load W tile (BN rows x BK cols of W[N,K]) -> Bs[k][n]
        {
            int n  = tid >> 2;   // 0..63
            int k4 = tid & 3;
            float4 v = *(const float4*)(W + (long long)(n0 + n) * K + k0 + k4 * 4);
            Bs[k4 * 4 + 0][n] = v.x;
            Bs[k4 * 4 + 1][n] = v.y;
            Bs[k4 * 4 + 2][n] = v.z;
            Bs[k4 * 4 + 3][n] = v.w;
        }
        __syncthreads();

#pragma unroll
        for (int k = 0; k < BK; k++) {
            // a pairs come packed for free: As row is M-contiguous, 16B aligned
            const ulonglong2* ap = (const ulonglong2*)&As[k][ty * 8];
            ulonglong2 a01 = ap[0];          // pairs (m0,m1), (m2,m3)
            ulonglong2 a23 = ap[1];          // pairs (m4,m5), (m6,m7)
            u64 a[4] = {a01.x, a01.y, a23.x, a23.y};
            float4 b4 = *(const float4*)&Bs[k][tx * 4];
            u64 bd[4] = {pack2(b4.x, b4.x), pack2(b4.y, b4.y),
                         pack2(b4.z, b4.z), pack2(b4.w, b4.w)};
#pragma unroll
            for (int p = 0; p < 4; p++)
#pragma unroll
                for (int j = 0; j < 4; j++)
                    acc[p][j] = ffma2(a[p], bd[j], acc[p][j]);
        }
        __syncthreads();
    }

    float bv[4] = {0.f, 0.f, 0.f, 0.f};
    if (MODE >= 1) {
        float4 b4 = *(const float4*)(bias + n0 + tx * 4);
        bv[0] = b4.x; bv[1] = b4.y; bv[2] = b4.z; bv[3] = b4.w;
    }
#pragma unroll
    for (int p = 0; p < 4; p++) {
#pragma unroll
        for (int half = 0; half < 2; half++) {
            int row = m0 + ty * 8 + 2 * p + half;
            if (row >= M) continue;
            float o[4];
#pragma unroll
            for (int j = 0; j < 4; j++) {
                float lo, hi;
                unpack2(acc[p][j], lo, hi);
                o[j] = half ? hi : lo;
            }
            float4 ov = make_float4(o[0], o[1], o[2], o[3]);
            if (MODE >= 1) { ov.x += bv[0]; ov.y += bv[1]; ov.z += bv[2]; ov.w += bv[3]; }
            if (MODE == 1) {
                ov.x = fmaxf(ov.x, 0.f); ov.y = fmaxf(ov.y, 0.f);
                ov.z = fmaxf(ov.z, 0.f); ov.w = fmaxf(ov.w, 0.f);
            }
            *(float4*)(C + (long long)row * N + n0 + tx * 4) = ov;
        }
    }
}

// Zero the masked rows of h1 (duplicates are idempotent). One block per index.
__global__ void mask_zero(float* __restrict__ h, const void* __restrict__ idx)
{
    long long r = load_idx(idx, blockIdx.x, g_is64);
    ((float4*)(h + r * HIDDEN))[threadIdx.x] = make_float4(0.f, 0.f, 0.f, 0.f);
}

// aggr[i] = h1[i] + E1[4] + E2[0]   (self-loop term; also serves as init)
__global__ __launch_bounds__(256)
void init_aggr(const float* __restrict__ h1, const float* __restrict__ E1,
               const float* __restrict__ E2, float* __restrict__ aggr)
{
    int idx = blockIdx.x * blockDim.x + threadIdx.x;    // over NNODES*64 float4
    if (idx >= NNODES * (HIDDEN / 4)) return;
    int c = idx & 63;
    float4 a  = ((const float4*)h1)[idx];
    float4 e1 = ((const float4*)(E1 + 4 * HIDDEN))[c];
    float4 e2 = ((const float4*)E2)[c];
    ((float4*)aggr)[idx] = make_float4(a.x + e1.x + e2.x, a.y + e1.y + e2.y,
                                       a.z + e1.z + e2.z, a.w + e1.w + e2.w);
}

// One warp per edge: aggr[dst] += x[src] + E1[a0] + E2[a1]  via vector red.
__global__ __launch_bounds__(256)
void edge_scatter(const float* __restrict__ x, const void* __restrict__ ei,
                  const void* __restrict__ ea, const float* __restrict__ E1,
                  const float* __restrict__ E2, float* __restrict__ aggr)
{
    int e = blockIdx.x * 8 + (threadIdx.x >> 5);
    if (e >= NEDGES) return;
    const int is64 = g_is64;
    int lane = threadIdx.x & 31;
    int src = (int)load_idx(ei, e, is64);
    int dst = (int)load_idx(ei, (long long)NEDGES + e, is64);
    int a0  = (int)load_idx(ea, 2LL * e, is64);
    int a1  = (int)load_idx(ea, 2LL * e + 1, is64);
    const float4* xs = (const float4*)(x + (long long)src * HIDDEN);
    const float4* p1 = (const float4*)(E1 + a0 * HIDDEN);
    const float4* p2 = (const float4*)(E2 + a1 * HIDDEN);
    float4* out = (float4*)(aggr + (long long)dst * HIDDEN);
#pragma unroll
    for (int i = 0; i < 2; i++) {
        int c = lane + 32 * i;
        float4 xv = xs[c], v1 = p1[c], v2 = p2[c];
        float4 m = make_float4(xv.x + v1.x + v2.x, xv.y + v1.y + v2.y,
                               xv.z + v1.z + v2.z, xv.w + v1.w + v2.w);
        red4(out + c, m);
    }
}

extern "C" void kernel_launch(void* const* d_in, const int* in_sizes, int n_in,
                              void* d_out, int out_size)
{
    const float* x     = (const float*)d_in[0];
    const void*  ei    = d_in[1];
    const void*  ea    = d_in[2];
    const void*  mask  = d_in[3];
    const float* pa    = (const float*)d_in[4];
    const float* W_enc = (const float*)d_in[5];
    const float* E1    = (const float*)d_in[6];
    const float* E2    = (const float*)d_in[7];
    const float* W1    = (const float*)d_in[8];
    const float* b1    = (const float*)d_in[9];
    const float* W2    = (const float*)d_in[10];
    const float* b2    = (const float*)d_in[11];
    float* out = (float*)d_out;

    float *h1, *aggr, *h2;
    cudaGetSymbolAddress((void**)&h1,   g_h1);
    cudaGetSymbolAddress((void**)&aggr, g_aggr);
    cudaGetSymbolAddress((void**)&h2,   g_h2);

    const int MB = (NNODES + 127) / 128;   // 157

    // 0) detect int32 vs int64 index dtype
    detect_idx_dtype<<<1, 1>>>((const int*)ei);

    // 1) h1 = prelu(x) @ W_enc^T
    sgemm128x64<0><<<dim3(HIDDEN / 64, MB), 256>>>(
        x, W_enc, nullptr, h1, NNODES, HIDDEN, HIDDEN, pa);

    // 2) zero masked rows
    mask_zero<<<2000, 64>>>(h1, mask);

    // 3) aggr = h1 + E1[4] + E2[0]  (self loops)
    init_aggr<<<(NNODES * (HIDDEN / 4) + 255) / 256, 256>>>(h1, E1, E2, aggr);

    // 4) aggr[dst] += h1[src] + E1[a0] + E2[a1]
    edge_scatter<<<(NEDGES + 7) / 8, 256>>>(h1, ei, ea, E1, E2, aggr);

    // 5) h2 = relu(aggr @ W1^T + b1)
    sgemm128x64<1><<<dim3(2 * HIDDEN / 64, MB), 256>>>(
        aggr, W1, b1, h2, NNODES, 2 * HIDDEN, HIDDEN, nullptr);

    // 6) out = h2 @ W2^T + b2
    sgemm128x64<2><<<dim3(HIDDEN / 64, MB), 256>>>(
        h2, W2, b2, out, NNODES, HIDDEN, 2 * HIDDEN, nullptr);
}

// round 8
// speedup vs baseline: 1.3841x; 1.3046x over previous
#include <cuda_runtime.h>
#include <cuda_bf16.h>
#include <cstdint>

#define HIDDEN 256
#define NNODES 20000
#define NEDGES 320000

typedef unsigned long long u64;

// ---------------- device global scratch (allocation-free rule) ----------------
__device__ __align__(16) float g_h1[NNODES * HIDDEN];     // enc output (fp32)
__device__ __align__(16) float g_aggr[NNODES * HIDDEN];   // segment sum (fp32)
__device__ __align__(16) __nv_bfloat16 g_x_hi[NNODES * HIDDEN];
__device__ __align__(16) __nv_bfloat16 g_x_lo[NNODES * HIDDEN];
__device__ __align__(16) __nv_bfloat16 g_ag_hi[NNODES * HIDDEN];
__device__ __align__(16) __nv_bfloat16 g_ag_lo[NNODES * HIDDEN];
__device__ __align__(16) __nv_bfloat16 g_h2_hi[NNODES * 2 * HIDDEN];
__device__ __align__(16) __nv_bfloat16 g_h2_lo[NNODES * 2 * HIDDEN];
__device__ __align__(16) __nv_bfloat16 g_We_hi[HIDDEN * HIDDEN];
__device__ __align__(16) __nv_bfloat16 g_We_lo[HIDDEN * HIDDEN];
__device__ __align__(16) __nv_bfloat16 g_W1_hi[2 * HIDDEN * HIDDEN];
__device__ __align__(16) __nv_bfloat16 g_W1_lo[2 * HIDDEN * HIDDEN];
__device__ __align__(16) __nv_bfloat16 g_W2_hi[HIDDEN * 2 * HIDDEN];
__device__ __align__(16) __nv_bfloat16 g_W2_lo[HIDDEN * 2 * HIDDEN];
__device__ int g_is64;

// ---------------- index dtype probe ----------------
__global__ void detect_idx_dtype(const int* __restrict__ ei_words)
{
    int is64 = 1;
    for (int i = 1; i < 64; i += 2)
        if (ei_words[i] != 0) { is64 = 0; break; }
    g_is64 = is64;
}
__device__ __forceinline__ long long load_idx(const void* p, long long i, int is64)
{
    return is64 ? ((const long long*)p)[i] : (long long)((const int*)p)[i];
}

__device__ __forceinline__ void red4(float4* addr, float4 v) {
    asm volatile("red.global.add.v4.f32 [%0], {%1, %2, %3, %4};"
                 :: "l"(addr), "f"(v.x), "f"(v.y), "f"(v.z), "f"(v.w)
                 : "memory");
}

__device__ __forceinline__ uint32_t smem_u32(const void* p) {
    uint32_t a;
    asm("{ .reg .u64 t; cvta.to.shared.u64 t, %1; cvt.u32.u64 %0, t; }"
        : "=r"(a) : "l"(p));
    return a;
}

// ---------------- hi/lo split ----------------
__device__ __forceinline__ void split1(float v, __nv_bfloat16& h, __nv_bfloat16& l) {
    h = __float2bfloat16(v);
    l = __float2bfloat16(v - __bfloat162float(h));
}

template <int PRELU>
__global__ __launch_bounds__(256)
void split_f32(const float* __restrict__ in, __nv_bfloat16* __restrict__ hi,
               __nv_bfloat16* __restrict__ lo, int n4, const float* __restrict__ pa)
{
    int i = blockIdx.x * 256 + threadIdx.x;
    if (i >= n4) return;
    float4 v = ((const float4*)in)[i];
    if (PRELU) {
        float a = *pa;
        v.x = v.x >= 0.f ? v.x : a * v.x;
        v.y = v.y >= 0.f ? v.y : a * v.y;
        v.z = v.z >= 0.f ? v.z : a * v.z;
        v.w = v.w >= 0.f ? v.w : a * v.w;
    }
    __nv_bfloat16 h[4], l[4];
    split1(v.x, h[0], l[0]); split1(v.y, h[1], l[1]);
    split1(v.z, h[2], l[2]); split1(v.w, h[3], l[3]);
    ((uint2*)hi)[i] = *(uint2*)h;
    ((uint2*)lo)[i] = *(uint2*)l;
}

// ---------------- mma.sync helpers ----------------
__device__ __forceinline__ void ldmat4(uint32_t& r0, uint32_t& r1, uint32_t& r2,
                                       uint32_t& r3, uint32_t addr) {
    asm volatile("ldmatrix.sync.aligned.m8n8.x4.shared.b16 {%0,%1,%2,%3}, [%4];"
                 : "=r"(r0), "=r"(r1), "=r"(r2), "=r"(r3) : "r"(addr));
}
__device__ __forceinline__ void mma16816(float& d0, float& d1, float& d2, float& d3,
                                         uint32_t a0, uint32_t a1, uint32_t a2, uint32_t a3,
                                         uint32_t b0, uint32_t b1) {
    asm volatile("mma.sync.aligned.m16n8k16.row.col.f32.bf16.bf16.f32 "
                 "{%0,%1,%2,%3}, {%4,%5,%6,%7}, {%8,%9}, {%0,%1,%2,%3};"
                 : "+f"(d0), "+f"(d1), "+f"(d2), "+f"(d3)
                 : "r"(a0), "r"(a1), "r"(a2), "r"(a3), "r"(b0), "r"(b1));
}

// ---------------------------------------------------------------------------
// bf16 hi/lo GEMM via mma.sync:  C[M,N] = A[M,K] @ W[N,K]^T (+bias/epilogue)
//   D = Ahi*Bhi + Ahi*Blo + Alo*Bhi  (fp32 accum)
// MODE 0: fp32 out | MODE 1: bias+ReLU -> bf16 hi/lo | MODE 2: bias -> fp32
// CTA 128x128, BK=32, 256 threads (8 warps, 2Mx4N), warp tile 64x32.
// W[N,K] is K-contiguous: B fragments load with NON-trans ldmatrix (n-rows).
// ---------------------------------------------------------------------------
#define SPAD 40   // smem row stride in bf16 (80 B: conflict-free ldmatrix)

template <int MODE>
__global__ __launch_bounds__(256)
void gemm_mma(const __nv_bfloat16* __restrict__ Ahi, const __nv_bfloat16* __restrict__ Alo,
              const __nv_bfloat16* __restrict__ Bhi, const __nv_bfloat16* __restrict__ Blo,
              const float* __restrict__ bias, float* __restrict__ Cf,
              __nv_bfloat16* __restrict__ Chi, __nv_bfloat16* __restrict__ Clo,
              int M, int N, int K)
{
    __shared__ __align__(16) __nv_bfloat16 As[2][128][SPAD];
    __shared__ __align__(16) __nv_bfloat16 Bs[2][128][SPAD];

    const int tid = threadIdx.x, lane = tid & 31, wid = tid >> 5;
    const int wm = wid >> 2, wn = wid & 3;     // warp grid 2(M) x 4(N)
    const int m0 = blockIdx.y * 128, n0 = blockIdx.x * 128;

    // ldmatrix per-lane offsets (same pattern for A and B: rows x k-cols)
    const int ra = lane & 7, mata = lane >> 3;
    const int aRow = ra + (mata & 1) * 8, aCol = (mata >> 1) * 8;

    const uint32_t as_base = smem_u32(&As[0][0][0]);
    const uint32_t bs_base = smem_u32(&Bs[0][0][0]);
    const uint32_t HALF = 128 * SPAD * 2;      // bytes per hi/lo tile

    float d[4][4][4];
#pragma unroll
    for (int i = 0; i < 4; i++)
#pragma unroll
        for (int j = 0; j < 4; j++)
#pragma unroll
            for (int k = 0; k < 4; k++) d[i][j][k] = 0.f;

    const int nchunks = K >> 5;
    for (int c = 0; c < nchunks; c++) {
        const int k0c = c << 5;
        // ---- gmem -> smem: 4 tiles of 128x32 bf16 ----
#pragma unroll
        for (int i = 0; i < 8; i++) {
            int q = tid + 256 * i;         // 0..2047
            int tile = q >> 9;             // 0:Ahi 1:Alo 2:Bhi 3:Blo
            int rem = q & 511;
            int r = rem >> 2, seg = rem & 3;
            uint4 v = make_uint4(0, 0, 0, 0);
            if (tile < 2) {
                int row = m0 + r;
                if (row < M)
                    v = *(const uint4*)((tile ? Alo : Ahi) + (size_t)row * K + k0c + seg * 8);
                *(uint4*)&As[tile][r][seg * 8] = v;
            } else {
                int row = n0 + r;
                v = *(const uint4*)((tile == 3 ? Blo : Bhi) + (size_t)row * K + k0c + seg * 8);
                *(uint4*)&Bs[tile - 2][r][seg * 8] = v;
            }
        }
        __syncthreads();

        // ---- 3 combos: (Ahi,Bhi), (Ahi,Blo), (Alo,Bhi) ----
#pragma unroll
        for (int combo = 0; combo < 3; combo++) {
            const uint32_t abase = as_base + (combo == 2 ? HALF : 0);
            const uint32_t bbase = bs_base + (combo == 1 ? HALF : 0);
#pragma unroll
            for (int ks = 0; ks < 2; ks++) {
                const int kk = ks * 16;
                uint32_t a[4][4];
#pragma unroll
                for (int mf = 0; mf < 4; mf++) {
                    uint32_t addr = abase +
                        ((wm * 64 + mf * 16 + aRow) * SPAD + kk + aCol) * 2;
                    ldmat4(a[mf][0], a[mf][1], a[mf][2], a[mf][3], addr);
                }
                // B: non-trans ldmatrix over W's n-rows.
                // regs: r0=(n0-7,k0-7) r1=(n8-15,k0-7) r2=(n0-7,k8-15) r3=(n8-15,k8-15)
                uint32_t b[2][4];
#pragma unroll
                for (int bf = 0; bf < 2; bf++) {
                    uint32_t addr = bbase +
                        ((wn * 32 + bf * 16 + aRow) * SPAD + kk + aCol) * 2;
                    ldmat4(b[bf][0], b[bf][1], b[bf][2], b[bf][3], addr);
                }
#pragma unroll
                for (int mf = 0; mf < 4; mf++)
#pragma unroll
                    for (int nf = 0; nf < 4; nf++)
                        mma16816(d[mf][nf][0], d[mf][nf][1], d[mf][nf][2], d[mf][nf][3],
                                 a[mf][0], a[mf][1], a[mf][2], a[mf][3],
                                 b[nf >> 1][(nf & 1)],          // k 0-7 half
                                 b[nf >> 1][(nf & 1) + 2]);     // k 8-15 half
            }
        }
        __syncthreads();
    }

    // ---- epilogue ----
#pragma unroll
    for (int mf = 0; mf < 4; mf++) {
        int row = m0 + wm * 64 + mf * 16 + (lane >> 2);
#pragma unroll
        for (int half = 0; half < 2; half++) {
            int r = row + half * 8;
            if (r >= M) continue;
#pragma unroll
            for (int nf = 0; nf < 4; nf++) {
                int col = n0 + wn * 32 + nf * 8 + (lane & 3) * 2;
                float v0 = d[mf][nf][half * 2], v1 = d[mf][nf][half * 2 + 1];
                if (MODE >= 1) {
                    v0 += __ldg(bias + col);
                    v1 += __ldg(bias + col + 1);
                }
                if (MODE == 1) {
                    v0 = fmaxf(v0, 0.f); v1 = fmaxf(v1, 0.f);
                    __nv_bfloat16 h0, l0, h1, l1;
                    split1(v0, h0, l0); split1(v1, h1, l1);
                    __nv_bfloat162 hh; hh.x = h0; hh.y = h1;
                    __nv_bfloat162 ll; ll.x = l0; ll.y = l1;
                    *(__nv_bfloat162*)(Chi + (size_t)r * N + col) = hh;
                    *(__nv_bfloat162*)(Clo + (size_t)r * N + col) = ll;
                } else {
                    *(float2*)(Cf + (size_t)r * N + col) = make_float2(v0, v1);
                }
            }
        }
    }
}

// ---------------- graph part ----------------
__global__ void mask_zero(float* __restrict__ h, const void* __restrict__ idx)
{
    long long r = load_idx(idx, blockIdx.x, g_is64);
    ((float4*)(h + r * HIDDEN))[threadIdx.x] = make_float4(0.f, 0.f, 0.f, 0.f);
}

__global__ __launch_bounds__(256)
void init_aggr(const float* __restrict__ h1, const float* __restrict__ E1,
               const float* __restrict__ E2, float* __restrict__ aggr)
{
    int idx = blockIdx.x * blockDim.x + threadIdx.x;
    if (idx >= NNODES * (HIDDEN / 4)) return;
    int c = idx & 63;
    float4 a  = ((const float4*)h1)[idx];
    float4 e1 = ((const float4*)(E1 + 4 * HIDDEN))[c];
    float4 e2 = ((const float4*)E2)[c];
    ((float4*)aggr)[idx] = make_float4(a.x + e1.x + e2.x, a.y + e1.y + e2.y,
                                       a.z + e1.z + e2.z, a.w + e1.w + e2.w);
}

__global__ __launch_bounds__(256)
void edge_scatter(const float* __restrict__ x, const void* __restrict__ ei,
                  const void* __restrict__ ea, const float* __restrict__ E1,
                  const float* __restrict__ E2, float* __restrict__ aggr)
{
    int e = blockIdx.x * 8 + (threadIdx.x >> 5);
    if (e >= NEDGES) return;
    const int is64 = g_is64;
    int lane = threadIdx.x & 31;
    int src = (int)load_idx(ei, e, is64);
    int dst = (int)load_idx(ei, (long long)NEDGES + e, is64);
    int a0  = (int)load_idx(ea, 2LL * e, is64);
    int a1  = (int)load_idx(ea, 2LL * e + 1, is64);
    const float4* xs = (const float4*)(x + (long long)src * HIDDEN);
    const float4* p1 = (const float4*)(E1 + a0 * HIDDEN);
    const float4* p2 = (const float4*)(E2 + a1 * HIDDEN);
    float4* out = (float4*)(aggr + (long long)dst * HIDDEN);
#pragma unroll
    for (int i = 0; i < 2; i++) {
        int c = lane + 32 * i;
        float4 xv = xs[c], v1 = p1[c], v2 = p2[c];
        float4 m = make_float4(xv.x + v1.x + v2.x, xv.y + v1.y + v2.y,
                               xv.z + v1.z + v2.z, xv.w + v1.w + v2.w);
        red4(out + c, m);
    }
}

extern "C" void kernel_launch(void* const* d_in, const int* in_sizes, int n_in,
                              void* d_out, int out_size)
{
    const float* x     = (const float*)d_in[0];
    const void*  ei    = d_in[1];
    const void*  ea    = d_in[2];
    const void*  mask  = d_in[3];
    const float* pa    = (const float*)d_in[4];
    const float* W_enc = (const float*)d_in[5];
    const float* E1    = (const float*)d_in[6];
    const float* E2    = (const float*)d_in[7];
    const float* W1    = (const float*)d_in[8];
    const float* b1    = (const float*)d_in[9];
    const float* W2    = (const float*)d_in[10];
    const float* b2    = (const float*)d_in[11];
    float* out = (float*)d_out;

    float *h1, *aggr;
    __nv_bfloat16 *xhi, *xlo, *aghi, *aglo, *h2hi, *h2lo;
    __nv_bfloat16 *Wehi, *Welo, *W1hi, *W1lo, *W2hi, *W2lo;
    cudaGetSymbolAddress((void**)&h1,   g_h1);
    cudaGetSymbolAddress((void**)&aggr, g_aggr);
    cudaGetSymbolAddress((void**)&xhi,  g_x_hi);
    cudaGetSymbolAddress((void**)&xlo,  g_x_lo);
    cudaGetSymbolAddress((void**)&aghi, g_ag_hi);
    cudaGetSymbolAddress((void**)&aglo, g_ag_lo);
    cudaGetSymbolAddress((void**)&h2hi, g_h2_hi);
    cudaGetSymbolAddress((void**)&h2lo, g_h2_lo);
    cudaGetSymbolAddress((void**)&Wehi, g_We_hi);
    cudaGetSymbolAddress((void**)&Welo, g_We_lo);
    cudaGetSymbolAddress((void**)&W1hi, g_W1_hi);
    cudaGetSymbolAddress((void**)&W1lo, g_W1_lo);
    cudaGetSymbolAddress((void**)&W2hi, g_W2_hi);
    cudaGetSymbolAddress((void**)&W2lo, g_W2_lo);

    const int MB = (NNODES + 127) / 128;   // 157

    // 0) index dtype probe
    detect_idx_dtype<<<1, 1>>>((const int*)ei);

    // 1) splits: x (with PReLU) + weights
    split_f32<1><<<(NNODES * HIDDEN / 4 + 255) / 256, 256>>>(x, xhi, xlo, NNODES * HIDDEN / 4, pa);
    split_f32<0><<<(HIDDEN * HIDDEN / 4 + 255) / 256, 256>>>(W_enc, Wehi, Welo, HIDDEN * HIDDEN / 4, nullptr);
    split_f32<0><<<(2 * HIDDEN * HIDDEN / 4 + 255) / 256, 256>>>(W1, W1hi, W1lo, 2 * HIDDEN * HIDDEN / 4, nullptr);
    split_f32<0><<<(2 * HIDDEN * HIDDEN / 4 + 255) / 256, 256>>>(W2, W2hi, W2lo, 2 * HIDDEN * HIDDEN / 4, nullptr);

    // 2) h1 = prelu(x) @ W_enc^T  (fp32 out)
    gemm_mma<0><<<dim3(HIDDEN / 128, MB), 256>>>(
        xhi, xlo, Wehi, Welo, nullptr, h1, nullptr, nullptr, NNODES, HIDDEN, HIDDEN);

    // 3) zero masked rows
    mask_zero<<<2000, 64>>>(h1, mask);

    // 4) aggr = h1 + E1[4] + E2[0]
    init_aggr<<<(NNODES * (HIDDEN / 4) + 255) / 256, 256>>>(h1, E1, E2, aggr);

    // 5) aggr[dst] += h1[src] + E1[a0] + E2[a1]
    edge_scatter<<<(NEDGES + 7) / 8, 256>>>(h1, ei, ea, E1, E2, aggr);

    // 6) split aggr -> bf16 hi/lo
    split_f32<0><<<(NNODES * HIDDEN / 4 + 255) / 256, 256>>>(aggr, aghi, aglo, NNODES * HIDDEN / 4, nullptr);

    // 7) h2 = relu(aggr @ W1^T + b1) -> bf16 hi/lo
    gemm_mma<1><<<dim3(2 * HIDDEN / 128, MB), 256>>>(
        aghi, aglo, W1hi, W1lo, b1, nullptr, h2hi, h2lo, NNODES, 2 * HIDDEN, HIDDEN);

    // 8) out = h2 @ W2^T + b2 (fp32)
    gemm_mma<2><<<dim3(HIDDEN / 128, MB), 256>>>(
        h2hi, h2lo, W2hi, W2lo, b2, out, nullptr, nullptr, NNODES, HIDDEN, 2 * HIDDEN);
}

// round 9
// speedup vs baseline: 1.6751x; 1.2103x over previous
#include <cuda_runtime.h>
#include <cuda_bf16.h>
#include <cstdint>

#define HIDDEN 256
#define NNODES 20000
#define NEDGES 320000

typedef unsigned long long u64;

// ---------------- device global scratch (allocation-free rule) ----------------
__device__ __align__(16) float g_h1[NNODES * HIDDEN];     // enc output (fp32)
__device__ __align__(16) float g_aggr[NNODES * HIDDEN];   // segment sum (fp32)
__device__ __align__(16) __nv_bfloat16 g_x_hi[NNODES * HIDDEN];
__device__ __align__(16) __nv_bfloat16 g_x_lo[NNODES * HIDDEN];
__device__ __align__(16) __nv_bfloat16 g_ag_hi[NNODES * HIDDEN];
__device__ __align__(16) __nv_bfloat16 g_ag_lo[NNODES * HIDDEN];
__device__ __align__(16) __nv_bfloat16 g_h2_hi[NNODES * 2 * HIDDEN];
__device__ __align__(16) __nv_bfloat16 g_h2_lo[NNODES * 2 * HIDDEN];
__device__ __align__(16) __nv_bfloat16 g_We_hi[HIDDEN * HIDDEN];
__device__ __align__(16) __nv_bfloat16 g_We_lo[HIDDEN * HIDDEN];
__device__ __align__(16) __nv_bfloat16 g_W1_hi[2 * HIDDEN * HIDDEN];
__device__ __align__(16) __nv_bfloat16 g_W1_lo[2 * HIDDEN * HIDDEN];
__device__ __align__(16) __nv_bfloat16 g_W2_hi[HIDDEN * 2 * HIDDEN];
__device__ __align__(16) __nv_bfloat16 g_W2_lo[HIDDEN * 2 * HIDDEN];
__device__ int g_is64;

// ---------------- index dtype probe ----------------
__global__ void detect_idx_dtype(const int* __restrict__ ei_words)
{
    int is64 = 1;
    for (int i = 1; i < 64; i += 2)
        if (ei_words[i] != 0) { is64 = 0; break; }
    g_is64 = is64;
}
__device__ __forceinline__ long long load_idx(const void* p, long long i, int is64)
{
    return is64 ? ((const long long*)p)[i] : (long long)((const int*)p)[i];
}

__device__ __forceinline__ void red4(float4* addr, float4 v) {
    asm volatile("red.global.add.v4.f32 [%0], {%1, %2, %3, %4};"
                 :: "l"(addr), "f"(v.x), "f"(v.y), "f"(v.z), "f"(v.w)
                 : "memory");
}

__device__ __forceinline__ uint32_t smem_u32(const void* p) {
    uint32_t a;
    asm("{ .reg .u64 t; cvta.to.shared.u64 t, %1; cvt.u32.u64 %0, t; }"
        : "=r"(a) : "l"(p));
    return a;
}

// cp.async 16B with zero-fill predicate (src-size=0 -> fill zeros)
__device__ __forceinline__ void cp16(uint32_t dst, const void* src, bool pred) {
    int sz = pred ? 16 : 0;
    asm volatile("cp.async.cg.shared.global [%0], [%1], 16, %2;"
                 :: "r"(dst), "l"(src), "r"(sz) : "memory");
}
#define CP_COMMIT() asm volatile("cp.async.commit_group;" ::: "memory")
#define CP_WAIT(n)  asm volatile("cp.async.wait_group %0;" :: "n"(n) : "memory")

// ---------------- hi/lo split ----------------
__device__ __forceinline__ void split1(float v, __nv_bfloat16& h, __nv_bfloat16& l) {
    h = __float2bfloat16(v);
    l = __float2bfloat16(v - __bfloat162float(h));
}

template <int PRELU>
__global__ __launch_bounds__(256)
void split_f32(const float* __restrict__ in, __nv_bfloat16* __restrict__ hi,
               __nv_bfloat16* __restrict__ lo, int n4, const float* __restrict__ pa)
{
    int i = blockIdx.x * 256 + threadIdx.x;
    if (i >= n4) return;
    float4 v = ((const float4*)in)[i];
    if (PRELU) {
        float a = *pa;
        v.x = v.x >= 0.f ? v.x : a * v.x;
        v.y = v.y >= 0.f ? v.y : a * v.y;
        v.z = v.z >= 0.f ? v.z : a * v.z;
        v.w = v.w >= 0.f ? v.w : a * v.w;
    }
    __nv_bfloat16 h[4], l[4];
    split1(v.x, h[0], l[0]); split1(v.y, h[1], l[1]);
    split1(v.z, h[2], l[2]); split1(v.w, h[3], l[3]);
    ((uint2*)hi)[i] = *(uint2*)h;
    ((uint2*)lo)[i] = *(uint2*)l;
}

// ---------------- mma.sync helpers ----------------
__device__ __forceinline__ void ldmat4(uint32_t& r0, uint32_t& r1, uint32_t& r2,
                                       uint32_t& r3, uint32_t addr) {
    asm volatile("ldmatrix.sync.aligned.m8n8.x4.shared.b16 {%0,%1,%2,%3}, [%4];"
                 : "=r"(r0), "=r"(r1), "=r"(r2), "=r"(r3) : "r"(addr));
}
__device__ __forceinline__ void mma16816(float& d0, float& d1, float& d2, float& d3,
                                         uint32_t a0, uint32_t a1, uint32_t a2, uint32_t a3,
                                         uint32_t b0, uint32_t b1) {
    asm volatile("mma.sync.aligned.m16n8k16.row.col.f32.bf16.bf16.f32 "
                 "{%0,%1,%2,%3}, {%4,%5,%6,%7}, {%8,%9}, {%0,%1,%2,%3};"
                 : "+f"(d0), "+f"(d1), "+f"(d2), "+f"(d3)
                 : "r"(a0), "r"(a1), "r"(a2), "r"(a3), "r"(b0), "r"(b1));
}

// ---------------------------------------------------------------------------
// bf16 hi/lo GEMM, cp.async double-buffered:
//   C[M,N] = A[M,K] @ W[N,K]^T ; D = Ahi*Bhi + Ahi*Blo + Alo*Bhi (fp32 accum)
// MODE 0: fp32 out | MODE 1: bias+ReLU -> bf16 hi/lo | MODE 2: bias -> fp32
// CTA 128x128, BK=32, 256 threads (8 warps, 2Mx4N), warp tile 64x32.
// ---------------------------------------------------------------------------
#define SPAD 40                  // smem row stride in bf16 (80 B, conflict-free)
#define TILE_B (128 * SPAD * 2)  // 10240 B per 128x32 tile
#define STG_B  (4 * TILE_B)      // 40960 B per stage (Ahi,Alo,Bhi,Blo)

template <int MODE>
__global__ __launch_bounds__(256)
void gemm_mma(const __nv_bfloat16* __restrict__ Ahi, const __nv_bfloat16* __restrict__ Alo,
              const __nv_bfloat16* __restrict__ Bhi, const __nv_bfloat16* __restrict__ Blo,
              const float* __restrict__ bias, float* __restrict__ Cf,
              __nv_bfloat16* __restrict__ Chi, __nv_bfloat16* __restrict__ Clo,
              int M, int N, int K)
{
    extern __shared__ __align__(16) char smem[];
    const uint32_t sb = smem_u32(smem);

    const int tid = threadIdx.x, lane = tid & 31, wid = tid >> 5;
    const int wm = wid >> 2, wn = wid & 3;     // warp grid 2(M) x 4(N)
    const int m0 = blockIdx.y * 128, n0 = blockIdx.x * 128;

    // ldmatrix per-lane offsets (rows x k-cols pattern for both A and B)
    const int ra = lane & 7, mata = lane >> 3;
    const int aRow = ra + (mata & 1) * 8, aCol = (mata >> 1) * 8;

    float d[4][4][4];
#pragma unroll
    for (int i = 0; i < 4; i++)
#pragma unroll
        for (int j = 0; j < 4; j++)
#pragma unroll
            for (int k = 0; k < 4; k++) d[i][j][k] = 0.f;

    const int nchunks = K >> 5;

    // ---- stage loader: 4 tiles of 128x32 bf16 via cp.async ----
    auto load_stage = [&](int c, int buf) {
        const int k0c = c << 5;
        const uint32_t st = sb + buf * STG_B;
#pragma unroll
        for (int i = 0; i < 8; i++) {
            int q = tid + 256 * i;         // 0..2047
            int tile = q >> 9;             // 0:Ahi 1:Alo 2:Bhi 3:Blo
            int rem = q & 511;
            int r = rem >> 2, seg = rem & 3;
            uint32_t dst = st + tile * TILE_B + (r * SPAD + seg * 8) * 2;
            if (tile < 2) {
                int row = m0 + r;
                bool ok = row < M;
                const __nv_bfloat16* src =
                    (tile ? Alo : Ahi) + (size_t)(ok ? row : 0) * K + k0c + seg * 8;
                cp16(dst, src, ok);
            } else {
                const __nv_bfloat16* src =
                    (tile == 3 ? Blo : Bhi) + (size_t)(n0 + r) * K + k0c + seg * 8;
                cp16(dst, src, true);
            }
        }
        CP_COMMIT();
    };

    load_stage(0, 0);

    for (int c = 0; c < nchunks; c++) {
        if (c + 1 < nchunks) load_stage(c + 1, (c + 1) & 1);
        if (c + 1 < nchunks) { CP_WAIT(1); } else { CP_WAIT(0); }
        __syncthreads();

        const uint32_t st = sb + (c & 1) * STG_B;
        const uint32_t sAhi = st, sAlo = st + TILE_B;
        const uint32_t sBhi = st + 2 * TILE_B, sBlo = st + 3 * TILE_B;

#pragma unroll
        for (int ks = 0; ks < 2; ks++) {
            const int kk = ks * 16;
            const uint32_t acolb = (kk + aCol) * 2;

            uint32_t a[4][4];
#pragma unroll
            for (int mf = 0; mf < 4; mf++)
                ldmat4(a[mf][0], a[mf][1], a[mf][2], a[mf][3],
                       sAhi + (wm * 64 + mf * 16 + aRow) * (SPAD * 2) + acolb);
            uint32_t bh[2][4], bl[2][4];
#pragma unroll
            for (int bf = 0; bf < 2; bf++) {
                ldmat4(bh[bf][0], bh[bf][1], bh[bf][2], bh[bf][3],
                       sBhi + (wn * 32 + bf * 16 + aRow) * (SPAD * 2) + acolb);
                ldmat4(bl[bf][0], bl[bf][1], bl[bf][2], bl[bf][3],
                       sBlo + (wn * 32 + bf * 16 + aRow) * (SPAD * 2) + acolb);
            }
            // combo 0: Ahi x Bhi ; combo 1: Ahi x Blo
#pragma unroll
            for (int mf = 0; mf < 4; mf++)
#pragma unroll
                for (int nf = 0; nf < 4; nf++) {
                    mma16816(d[mf][nf][0], d[mf][nf][1], d[mf][nf][2], d[mf][nf][3],
                             a[mf][0], a[mf][1], a[mf][2], a[mf][3],
                             bh[nf >> 1][(nf & 1)], bh[nf >> 1][(nf & 1) + 2]);
                    mma16816(d[mf][nf][0], d[mf][nf][1], d[mf][nf][2], d[mf][nf][3],
                             a[mf][0], a[mf][1], a[mf][2], a[mf][3],
                             bl[nf >> 1][(nf & 1)], bl[nf >> 1][(nf & 1) + 2]);
                }
            // combo 2: Alo x Bhi (reuse a[] registers)
#pragma unroll
            for (int mf = 0; mf < 4; mf++)
                ldmat4(a[mf][0], a[mf][1], a[mf][2], a[mf][3],
                       sAlo + (wm * 64 + mf * 16 + aRow) * (SPAD * 2) + acolb);
#pragma unroll
            for (int mf = 0; mf < 4; mf++)
#pragma unroll
                for (int nf = 0; nf < 4; nf++)
                    mma16816(d[mf][nf][0], d[mf][nf][1], d[mf][nf][2], d[mf][nf][3],
                             a[mf][0], a[mf][1], a[mf][2], a[mf][3],
                             bh[nf >> 1][(nf & 1)], bh[nf >> 1][(nf & 1) + 2]);
        }
        __syncthreads();
    }

    // ---- epilogue ----
#pragma unroll
    for (int mf = 0; mf < 4; mf++) {
        int row = m0 + wm * 64 + mf * 16 + (lane >> 2);
#pragma unroll
        for (int half = 0; half < 2; half++) {
            int r = row + half * 8;
            if (r >= M) continue;
#pragma unroll
            for (int nf = 0; nf < 4; nf++) {
                int col = n0 + wn * 32 + nf * 8 + (lane & 3) * 2;
                float v0 = d[mf][nf][half * 2], v1 = d[mf][nf][half * 2 + 1];
                if (MODE >= 1) {
                    v0 += __ldg(bias + col);
                    v1 += __ldg(bias + col + 1);
                }
                if (MODE == 1) {
                    v0 = fmaxf(v0, 0.f); v1 = fmaxf(v1, 0.f);
                    __nv_bfloat16 h0, l0, h1, l1;
                    split1(v0, h0, l0); split1(v1, h1, l1);
                    __nv_bfloat162 hh; hh.x = h0; hh.y = h1;
                    __nv_bfloat162 ll; ll.x = l0; ll.y = l1;
                    *(__nv_bfloat162*)(Chi + (size_t)r * N + col) = hh;
                    *(__nv_bfloat162*)(Clo + (size_t)r * N + col) = ll;
                } else {
                    *(float2*)(Cf + (size_t)r * N + col) = make_float2(v0, v1);
                }
            }
        }
    }
}

// ---------------- graph part ----------------
__global__ void mask_zero(float* __restrict__ h, const void* __restrict__ idx)
{
    long long r = load_idx(idx, blockIdx.x, g_is64);
    ((float4*)(h + r * HIDDEN))[threadIdx.x] = make_float4(0.f, 0.f, 0.f, 0.f);
}

__global__ __launch_bounds__(256)
void init_aggr(const float* __restrict__ h1, const float* __restrict__ E1,
               const float* __restrict__ E2, float* __restrict__ aggr)
{
    int idx = blockIdx.x * blockDim.x + threadIdx.x;
    if (idx >= NNODES * (HIDDEN / 4)) return;
    int c = idx & 63;
    float4 a  = ((const float4*)h1)[idx];
    float4 e1 = ((const float4*)(E1 + 4 * HIDDEN))[c];
    float4 e2 = ((const float4*)E2)[c];
    ((float4*)aggr)[idx] = make_float4(a.x + e1.x + e2.x, a.y + e1.y + e2.y,
                                       a.z + e1.z + e2.z, a.w + e1.w + e2.w);
}

__global__ __launch_bounds__(256)
void edge_scatter(const float* __restrict__ x, const void* __restrict__ ei,
                  const void* __restrict__ ea, const float* __restrict__ E1,
                  const float* __restrict__ E2, float* __restrict__ aggr)
{
    int e = blockIdx.x * 8 + (threadIdx.x >> 5);
    if (e >= NEDGES) return;
    const int is64 = g_is64;
    int lane = threadIdx.x & 31;
    int src = (int)load_idx(ei, e, is64);
    int dst = (int)load_idx(ei, (long long)NEDGES + e, is64);
    int a0  = (int)load_idx(ea, 2LL * e, is64);
    int a1  = (int)load_idx(ea, 2LL * e + 1, is64);
    const float4* xs = (const float4*)(x + (long long)src * HIDDEN);
    const float4* p1 = (const float4*)(E1 + a0 * HIDDEN);
    const float4* p2 = (const float4*)(E2 + a1 * HIDDEN);
    float4* out = (float4*)(aggr + (long long)dst * HIDDEN);
#pragma unroll
    for (int i = 0; i < 2; i++) {
        int c = lane + 32 * i;
        float4 xv = xs[c], v1 = p1[c], v2 = p2[c];
        float4 m = make_float4(xv.x + v1.x + v2.x, xv.y + v1.y + v2.y,
                               xv.z + v1.z + v2.z, xv.w + v1.w + v2.w);
        red4(out + c, m);
    }
}

extern "C" void kernel_launch(void* const* d_in, const int* in_sizes, int n_in,
                              void* d_out, int out_size)
{
    const float* x     = (const float*)d_in[0];
    const void*  ei    = d_in[1];
    const void*  ea    = d_in[2];
    const void*  mask  = d_in[3];
    const float* pa    = (const float*)d_in[4];
    const float* W_enc = (const float*)d_in[5];
    const float* E1    = (const float*)d_in[6];
    const float* E2    = (const float*)d_in[7];
    const float* W1    = (const float*)d_in[8];
    const float* b1    = (const float*)d_in[9];
    const float* W2    = (const float*)d_in[10];
    const float* b2    = (const float*)d_in[11];
    float* out = (float*)d_out;

    float *h1, *aggr;
    __nv_bfloat16 *xhi, *xlo, *aghi, *aglo, *h2hi, *h2lo;
    __nv_bfloat16 *Wehi, *Welo, *W1hi, *W1lo, *W2hi, *W2lo;
    cudaGetSymbolAddress((void**)&h1,   g_h1);
    cudaGetSymbolAddress((void**)&aggr, g_aggr);
    cudaGetSymbolAddress((void**)&xhi,  g_x_hi);
    cudaGetSymbolAddress((void**)&xlo,  g_x_lo);
    cudaGetSymbolAddress((void**)&aghi, g_ag_hi);
    cudaGetSymbolAddress((void**)&aglo, g_ag_lo);
    cudaGetSymbolAddress((void**)&h2hi, g_h2_hi);
    cudaGetSymbolAddress((void**)&h2lo, g_h2_lo);
    cudaGetSymbolAddress((void**)&Wehi, g_We_hi);
    cudaGetSymbolAddress((void**)&Welo, g_We_lo);
    cudaGetSymbolAddress((void**)&W1hi, g_W1_hi);
    cudaGetSymbolAddress((void**)&W1lo, g_W1_lo);
    cudaGetSymbolAddress((void**)&W2hi, g_W2_hi);
    cudaGetSymbolAddress((void**)&W2lo, g_W2_lo);

    const int SMEM_SZ = 2 * STG_B;   // 81920
    cudaFuncSetAttribute(gemm_mma<0>, cudaFuncAttributeMaxDynamicSharedMemorySize, SMEM_SZ);
    cudaFuncSetAttribute(gemm_mma<1>, cudaFuncAttributeMaxDynamicSharedMemorySize, SMEM_SZ);
    cudaFuncSetAttribute(gemm_mma<2>, cudaFuncAttributeMaxDynamicSharedMemorySize, SMEM_SZ);

    const int MB = (NNODES + 127) / 128;   // 157

    // 0) index dtype probe
    detect_idx_dtype<<<1, 1>>>((const int*)ei);

    // 1) splits: x (with PReLU) + weights
    split_f32<1><<<(NNODES * HIDDEN / 4 + 255) / 256, 256>>>(x, xhi, xlo, NNODES * HIDDEN / 4, pa);
    split_f32<0><<<(HIDDEN * HIDDEN / 4 + 255) / 256, 256>>>(W_enc, Wehi, Welo, HIDDEN * HIDDEN / 4, nullptr);
    split_f32<0><<<(2 * HIDDEN * HIDDEN / 4 + 255) / 256, 256>>>(W1, W1hi, W1lo, 2 * HIDDEN * HIDDEN / 4, nullptr);
    split_f32<0><<<(2 * HIDDEN * HIDDEN / 4 + 255) / 256, 256>>>(W2, W2hi, W2lo, 2 * HIDDEN * HIDDEN / 4, nullptr);

    // 2) h1 = prelu(x) @ W_enc^T  (fp32 out)
    gemm_mma<0><<<dim3(HIDDEN / 128, MB), 256, SMEM_SZ>>>(
        xhi, xlo, Wehi, Welo, nullptr, h1, nullptr, nullptr, NNODES, HIDDEN, HIDDEN);

    // 3) zero masked rows
    mask_zero<<<2000, 64>>>(h1, mask);

    // 4) aggr = h1 + E1[4] + E2[0]
    init_aggr<<<(NNODES * (HIDDEN / 4) + 255) / 256, 256>>>(h1, E1, E2, aggr);

    // 5) aggr[dst] += h1[src] + E1[a0] + E2[a1]
    edge_scatter<<<(NEDGES + 7) / 8, 256>>>(h1, ei, ea, E1, E2, aggr);

    // 6) split aggr -> bf16 hi/lo
    split_f32<0><<<(NNODES * HIDDEN / 4 + 255) / 256, 256>>>(aggr, aghi, aglo, NNODES * HIDDEN / 4, nullptr);

    // 7) h2 = relu(aggr @ W1^T + b1) -> bf16 hi/lo
    gemm_mma<1><<<dim3(2 * HIDDEN / 128, MB), 256, SMEM_SZ>>>(
        aghi, aglo, W1hi, W1lo, b1, nullptr, h2hi, h2lo, NNODES, 2 * HIDDEN, HIDDEN);

    // 8) out = h2 @ W2^T + b2 (fp32)
    gemm_mma<2><<<dim3(HIDDEN / 128, MB), 256, SMEM_SZ>>>(
        h2hi, h2lo, W2hi, W2lo, b2, out, nullptr, nullptr, NNODES, HIDDEN, 2 * HIDDEN);
}

// round 10
// speedup vs baseline: 1.7680x; 1.0554x over previous
#include <cuda_runtime.h>
#include <cuda_bf16.h>
#include <cstdint>

#define HIDDEN 256
#define NNODES 20000
#define NEDGES 320000

typedef unsigned long long u64;

// ---------------- device global scratch (allocation-free rule) ----------------
__device__ __align__(16) float g_h1[NNODES * HIDDEN];     // enc output (fp32)
__device__ __align__(16) float g_aggr[NNODES * HIDDEN];   // segment sum (fp32)
__device__ __align__(16) __nv_bfloat16 g_x_hi[NNODES * HIDDEN];
__device__ __align__(16) __nv_bfloat16 g_x_lo[NNODES * HIDDEN];
__device__ __align__(16) __nv_bfloat16 g_ag_hi[NNODES * HIDDEN];
__device__ __align__(16) __nv_bfloat16 g_ag_lo[NNODES * HIDDEN];
__device__ __align__(16) __nv_bfloat16 g_h2_hi[NNODES * 2 * HIDDEN];
__device__ __align__(16) __nv_bfloat16 g_h2_lo[NNODES * 2 * HIDDEN];
__device__ __align__(16) __nv_bfloat16 g_We_hi[HIDDEN * HIDDEN];
__device__ __align__(16) __nv_bfloat16 g_We_lo[HIDDEN * HIDDEN];
__device__ __align__(16) __nv_bfloat16 g_W1_hi[2 * HIDDEN * HIDDEN];
__device__ __align__(16) __nv_bfloat16 g_W1_lo[2 * HIDDEN * HIDDEN];
__device__ __align__(16) __nv_bfloat16 g_W2_hi[HIDDEN * 2 * HIDDEN];
__device__ __align__(16) __nv_bfloat16 g_W2_lo[HIDDEN * 2 * HIDDEN];
__device__ int g_is64;

// ---------------- index dtype probe ----------------
__global__ void detect_idx_dtype(const int* __restrict__ ei_words)
{
    int is64 = 1;
    for (int i = 1; i < 64; i += 2)
        if (ei_words[i] != 0) { is64 = 0; break; }
    g_is64 = is64;
}
__device__ __forceinline__ long long load_idx(const void* p, long long i, int is64)
{
    return is64 ? ((const long long*)p)[i] : (long long)((const int*)p)[i];
}

__device__ __forceinline__ void red4(float4* addr, float4 v) {
    asm volatile("red.global.add.v4.f32 [%0], {%1, %2, %3, %4};"
                 :: "l"(addr), "f"(v.x), "f"(v.y), "f"(v.z), "f"(v.w)
                 : "memory");
}

__device__ __forceinline__ uint32_t smem_u32(const void* p) {
    uint32_t a;
    asm("{ .reg .u64 t; cvta.to.shared.u64 t, %1; cvt.u32.u64 %0, t; }"
        : "=r"(a) : "l"(p));
    return a;
}

// cp.async 16B with zero-fill predicate (src-size=0 -> fill zeros)
__device__ __forceinline__ void cp16(uint32_t dst, const void* src, bool pred) {
    int sz = pred ? 16 : 0;
    asm volatile("cp.async.cg.shared.global [%0], [%1], 16, %2;"
                 :: "r"(dst), "l"(src), "r"(sz) : "memory");
}
#define CP_COMMIT() asm volatile("cp.async.commit_group;" ::: "memory")
#define CP_WAIT(n)  asm volatile("cp.async.wait_group %0;" :: "n"(n) : "memory")

// SW128-style swizzle inside an 8KB tile:
// logical (row r in 0..127, byte c in 0..63) -> packed 64 x 128B rows
__device__ __forceinline__ uint32_t tile_off(int r, int c) {
    uint32_t off = (uint32_t)((r & 63) * 128 + ((r >> 6) << 6) + c);
    return off ^ ((off >> 3) & 0x70);
}

// ---------------- hi/lo split ----------------
__device__ __forceinline__ void split1(float v, __nv_bfloat16& h, __nv_bfloat16& l) {
    h = __float2bfloat16(v);
    l = __float2bfloat16(v - __bfloat162float(h));
}

template <int PRELU>
__global__ __launch_bounds__(256)
void split_f32(const float* __restrict__ in, __nv_bfloat16* __restrict__ hi,
               __nv_bfloat16* __restrict__ lo, int n4, const float* __restrict__ pa)
{
    int i = blockIdx.x * 256 + threadIdx.x;
    if (i >= n4) return;
    float4 v = ((const float4*)in)[i];
    if (PRELU) {
        float a = *pa;
        v.x = v.x >= 0.f ? v.x : a * v.x;
        v.y = v.y >= 0.f ? v.y : a * v.y;
        v.z = v.z >= 0.f ? v.z : a * v.z;
        v.w = v.w >= 0.f ? v.w : a * v.w;
    }
    __nv_bfloat16 h[4], l[4];
    split1(v.x, h[0], l[0]); split1(v.y, h[1], l[1]);
    split1(v.z, h[2], l[2]); split1(v.w, h[3], l[3]);
    ((uint2*)hi)[i] = *(uint2*)h;
    ((uint2*)lo)[i] = *(uint2*)l;
}

// ---------------- mma.sync helpers ----------------
__device__ __forceinline__ void ldmat4(uint32_t& r0, uint32_t& r1, uint32_t& r2,
                                       uint32_t& r3, uint32_t addr) {
    asm volatile("ldmatrix.sync.aligned.m8n8.x4.shared.b16 {%0,%1,%2,%3}, [%4];"
                 : "=r"(r0), "=r"(r1), "=r"(r2), "=r"(r3) : "r"(addr));
}
__device__ __forceinline__ void mma16816(float& d0, float& d1, float& d2, float& d3,
                                         uint32_t a0, uint32_t a1, uint32_t a2, uint32_t a3,
                                         uint32_t b0, uint32_t b1) {
    asm volatile("mma.sync.aligned.m16n8k16.row.col.f32.bf16.bf16.f32 "
                 "{%0,%1,%2,%3}, {%4,%5,%6,%7}, {%8,%9}, {%0,%1,%2,%3};"
                 : "+f"(d0), "+f"(d1), "+f"(d2), "+f"(d3)
                 : "r"(a0), "r"(a1), "r"(a2), "r"(a3), "r"(b0), "r"(b1));
}

// ---------------------------------------------------------------------------
// bf16 hi/lo GEMM, cp.async double-buffered, swizzled smem (3 CTAs/SM):
//   C[M,N] = A[M,K] @ W[N,K]^T ; D = Ahi*Bhi + Ahi*Blo + Alo*Bhi (fp32 accum)
// MODE 0: fp32 out | MODE 1: bias+ReLU -> bf16 hi/lo | MODE 2: bias -> fp32
// CTA 128x128, BK=32, 256 threads (8 warps, 2Mx4N), warp tile 64x32.
// ---------------------------------------------------------------------------
#define TILE_B 8192              // 128x32 bf16 packed as 64 x 128B (swizzled)
#define STG_B  (4 * TILE_B)      // 32768 B per stage (Ahi,Alo,Bhi,Blo)

template <int MODE>
__global__ __launch_bounds__(256)
void gemm_mma(const __nv_bfloat16* __restrict__ Ahi, const __nv_bfloat16* __restrict__ Alo,
              const __nv_bfloat16* __restrict__ Bhi, const __nv_bfloat16* __restrict__ Blo,
              const float* __restrict__ bias, float* __restrict__ Cf,
              __nv_bfloat16* __restrict__ Chi, __nv_bfloat16* __restrict__ Clo,
              int M, int N, int K)
{
    extern __shared__ __align__(1024) char smem[];
    const uint32_t sb = smem_u32(smem);

    const int tid = threadIdx.x, lane = tid & 31, wid = tid >> 5;
    const int wm = wid >> 2, wn = wid & 3;     // warp grid 2(M) x 4(N)
    const int m0 = blockIdx.y * 128, n0 = blockIdx.x * 128;

    // ldmatrix per-lane offsets (rows x k-cols pattern for both A and B)
    const int ra = lane & 7, mata = lane >> 3;
    const int aRow = ra + (mata & 1) * 8, aCol = (mata >> 1) * 8;   // aCol in bf16

    float d[4][4][4];
#pragma unroll
    for (int i = 0; i < 4; i++)
#pragma unroll
        for (int j = 0; j < 4; j++)
#pragma unroll
            for (int k = 0; k < 4; k++) d[i][j][k] = 0.f;

    const int nchunks = K >> 5;

    // ---- stage loader: 4 tiles of 128x32 bf16 via cp.async, swizzled ----
    auto load_stage = [&](int c, int buf) {
        const int k0c = c << 5;
        const uint32_t st = sb + buf * STG_B;
#pragma unroll
        for (int i = 0; i < 8; i++) {
            int q = tid + 256 * i;         // 0..2047
            int tile = q >> 9;             // 0:Ahi 1:Alo 2:Bhi 3:Blo
            int rem = q & 511;
            int r = rem >> 2, seg = rem & 3;
            uint32_t dst = st + tile * TILE_B + tile_off(r, seg * 16);
            if (tile < 2) {
                int row = m0 + r;
                bool ok = row < M;
                const __nv_bfloat16* src =
                    (tile ? Alo : Ahi) + (size_t)(ok ? row : 0) * K + k0c + seg * 8;
                cp16(dst, src, ok);
            } else {
                const __nv_bfloat16* src =
                    (tile == 3 ? Blo : Bhi) + (size_t)(n0 + r) * K + k0c + seg * 8;
                cp16(dst, src, true);
            }
        }
        CP_COMMIT();
    };

    load_stage(0, 0);

    for (int c = 0; c < nchunks; c++) {
        if (c + 1 < nchunks) load_stage(c + 1, (c + 1) & 1);
        if (c + 1 < nchunks) { CP_WAIT(1); } else { CP_WAIT(0); }
        __syncthreads();

        const uint32_t st = sb + (c & 1) * STG_B;
        const uint32_t sAhi = st, sAlo = st + TILE_B;
        const uint32_t sBhi = st + 2 * TILE_B, sBlo = st + 3 * TILE_B;

#pragma unroll
        for (int ks = 0; ks < 2; ks++) {
            const int kk = ks * 16;
            const int cb = (kk + aCol) * 2;    // byte col within 64B logical row

            uint32_t a[4][4];
#pragma unroll
            for (int mf = 0; mf < 4; mf++)
                ldmat4(a[mf][0], a[mf][1], a[mf][2], a[mf][3],
                       sAhi + tile_off(wm * 64 + mf * 16 + aRow, cb));
            uint32_t bh[2][4], bl[2][4];
#pragma unroll
            for (int bf = 0; bf < 2; bf++) {
                ldmat4(bh[bf][0], bh[bf][1], bh[bf][2], bh[bf][3],
                       sBhi + tile_off(wn * 32 + bf * 16 + aRow, cb));
                ldmat4(bl[bf][0], bl[bf][1], bl[bf][2], bl[bf][3],
                       sBlo + tile_off(wn * 32 + bf * 16 + aRow, cb));
            }
            // combo 0: Ahi x Bhi ; combo 1: Ahi x Blo
#pragma unroll
            for (int mf = 0; mf < 4; mf++)
#pragma unroll
                for (int nf = 0; nf < 4; nf++) {
                    mma16816(d[mf][nf][0], d[mf][nf][1], d[mf][nf][2], d[mf][nf][3],
                             a[mf][0], a[mf][1], a[mf][2], a[mf][3],
                             bh[nf >> 1][(nf & 1)], bh[nf >> 1][(nf & 1) + 2]);
                    mma16816(d[mf][nf][0], d[mf][nf][1], d[mf][nf][2], d[mf][nf][3],
                             a[mf][0], a[mf][1], a[mf][2], a[mf][3],
                             bl[nf >> 1][(nf & 1)], bl[nf >> 1][(nf & 1) + 2]);
                }
            // combo 2: Alo x Bhi (reuse a[] registers)
#pragma unroll
            for (int mf = 0; mf < 4; mf++)
                ldmat4(a[mf][0], a[mf][1], a[mf][2], a[mf][3],
                       sAlo + tile_off(wm * 64 + mf * 16 + aRow, cb));
#pragma unroll
            for (int mf = 0; mf < 4; mf++)
#pragma unroll
                for (int nf = 0; nf < 4; nf++)
                    mma16816(d[mf][nf][0], d[mf][nf][1], d[mf][nf][2], d[mf][nf][3],
                             a[mf][0], a[mf][1], a[mf][2], a[mf][3],
                             bh[nf >> 1][(nf & 1)], bh[nf >> 1][(nf & 1) + 2]);
        }
        __syncthreads();
    }

    // ---- epilogue ----
#pragma unroll
    for (int mf = 0; mf < 4; mf++) {
        int row = m0 + wm * 64 + mf * 16 + (lane >> 2);
#pragma unroll
        for (int half = 0; half < 2; half++) {
            int r = row + half * 8;
            if (r >= M) continue;
#pragma unroll
            for (int nf = 0; nf < 4; nf++) {
                int col = n0 + wn * 32 + nf * 8 + (lane & 3) * 2;
                float v0 = d[mf][nf][half * 2], v1 = d[mf][nf][half * 2 + 1];
                if (MODE >= 1) {
                    v0 += __ldg(bias + col);
                    v1 += __ldg(bias + col + 1);
                }
                if (MODE == 1) {
                    v0 = fmaxf(v0, 0.f); v1 = fmaxf(v1, 0.f);
                    __nv_bfloat16 h0, l0, h1, l1;
                    split1(v0, h0, l0); split1(v1, h1, l1);
                    __nv_bfloat162 hh; hh.x = h0; hh.y = h1;
                    __nv_bfloat162 ll; ll.x = l0; ll.y = l1;
                    *(__nv_bfloat162*)(Chi + (size_t)r * N + col) = hh;
                    *(__nv_bfloat162*)(Clo + (size_t)r * N + col) = ll;
                } else {
                    *(float2*)(Cf + (size_t)r * N + col) = make_float2(v0, v1);
                }
            }
        }
    }
}

// ---------------- graph part ----------------
__global__ void mask_zero(float* __restrict__ h, const void* __restrict__ idx)
{
    long long r = load_idx(idx, blockIdx.x, g_is64);
    ((float4*)(h + r * HIDDEN))[threadIdx.x] = make_float4(0.f, 0.f, 0.f, 0.f);
}

__global__ __launch_bounds__(256)
void init_aggr(const float* __restrict__ h1, const float* __restrict__ E1,
               const float* __restrict__ E2, float* __restrict__ aggr)
{
    int idx = blockIdx.x * blockDim.x + threadIdx.x;
    if (idx >= NNODES * (HIDDEN / 4)) return;
    int c = idx & 63;
    float4 a  = ((const float4*)h1)[idx];
    float4 e1 = ((const float4*)(E1 + 4 * HIDDEN))[c];
    float4 e2 = ((const float4*)E2)[c];
    ((float4*)aggr)[idx] = make_float4(a.x + e1.x + e2.x, a.y + e1.y + e2.y,
                                       a.z + e1.z + e2.z, a.w + e1.w + e2.w);
}

__global__ __launch_bounds__(256)
void edge_scatter(const float* __restrict__ x, const void* __restrict__ ei,
                  const void* __restrict__ ea, const float* __restrict__ E1,
                  const float* __restrict__ E2, float* __restrict__ aggr)
{
    int e = blockIdx.x * 8 + (threadIdx.x >> 5);
    if (e >= NEDGES) return;
    const int is64 = g_is64;
    int lane = threadIdx.x & 31;
    int src = (int)load_idx(ei, e, is64);
    int dst = (int)load_idx(ei, (long long)NEDGES + e, is64);
    int a0  = (int)load_idx(ea, 2LL * e, is64);
    int a1  = (int)load_idx(ea, 2LL * e + 1, is64);
    const float4* xs = (const float4*)(x + (long long)src * HIDDEN);
    const float4* p1 = (const float4*)(E1 + a0 * HIDDEN);
    const float4* p2 = (const float4*)(E2 + a1 * HIDDEN);
    float4* out = (float4*)(aggr + (long long)dst * HIDDEN);
#pragma unroll
    for (int i = 0; i < 2; i++) {
        int c = lane + 32 * i;
        float4 xv = xs[c], v1 = p1[c], v2 = p2[c];
        float4 m = make_float4(xv.x + v1.x + v2.x, xv.y + v1.y + v2.y,
                               xv.z + v1.z + v2.z, xv.w + v1.w + v2.w);
        red4(out + c, m);
    }
}

extern "C" void kernel_launch(void* const* d_in, const int* in_sizes, int n_in,
                              void* d_out, int out_size)
{
    const float* x     = (const float*)d_in[0];
    const void*  ei    = d_in[1];
    const void*  ea    = d_in[2];
    const void*  mask  = d_in[3];
    const float* pa    = (const float*)d_in[4];
    const float* W_enc = (const float*)d_in[5];
    const float* E1    = (const float*)d_in[6];
    const float* E2    = (const float*)d_in[7];
    const float* W1    = (const float*)d_in[8];
    const float* b1    = (const float*)d_in[9];
    const float* W2    = (const float*)d_in[10];
    const float* b2    = (const float*)d_in[11];
    float* out = (float*)d_out;

    float *h1, *aggr;
    __nv_bfloat16 *xhi, *xlo, *aghi, *aglo, *h2hi, *h2lo;
    __nv_bfloat16 *Wehi, *Welo, *W1hi, *W1lo, *W2hi, *W2lo;
    cudaGetSymbolAddress((void**)&h1,   g_h1);
    cudaGetSymbolAddress((void**)&aggr, g_aggr);
    cudaGetSymbolAddress((void**)&xhi,  g_x_hi);
    cudaGetSymbolAddress((void**)&xlo,  g_x_lo);
    cudaGetSymbolAddress((void**)&aghi, g_ag_hi);
    cudaGetSymbolAddress((void**)&aglo, g_ag_lo);
    cudaGetSymbolAddress((void**)&h2hi, g_h2_hi);
    cudaGetSymbolAddress((void**)&h2lo, g_h2_lo);
    cudaGetSymbolAddress((void**)&Wehi, g_We_hi);
    cudaGetSymbolAddress((void**)&Welo, g_We_lo);
    cudaGetSymbolAddress((void**)&W1hi, g_W1_hi);
    cudaGetSymbolAddress((void**)&W1lo, g_W1_lo);
    cudaGetSymbolAddress((void**)&W2hi, g_W2_hi);
    cudaGetSymbolAddress((void**)&W2lo, g_W2_lo);

    const int SMEM_SZ = 2 * STG_B;   // 65536
    cudaFuncSetAttribute(gemm_mma<0>, cudaFuncAttributeMaxDynamicSharedMemorySize, SMEM_SZ);
    cudaFuncSetAttribute(gemm_mma<1>, cudaFuncAttributeMaxDynamicSharedMemorySize, SMEM_SZ);
    cudaFuncSetAttribute(gemm_mma<2>, cudaFuncAttributeMaxDynamicSharedMemorySize, SMEM_SZ);

    const int MB = (NNODES + 127) / 128;   // 157

    // 0) index dtype probe
    detect_idx_dtype<<<1, 1>>>((const int*)ei);

    // 1) splits: x (with PReLU) + weights
    split_f32<1><<<(NNODES * HIDDEN / 4 + 255) / 256, 256>>>(x, xhi, xlo, NNODES * HIDDEN / 4, pa);
    split_f32<0><<<(HIDDEN * HIDDEN / 4 + 255) / 256, 256>>>(W_enc, Wehi, Welo, HIDDEN * HIDDEN / 4, nullptr);
    split_f32<0><<<(2 * HIDDEN * HIDDEN / 4 + 255) / 256, 256>>>(W1, W1hi, W1lo, 2 * HIDDEN * HIDDEN / 4, nullptr);
    split_f32<0><<<(2 * HIDDEN * HIDDEN / 4 + 255) / 256, 256>>>(W2, W2hi, W2lo, 2 * HIDDEN * HIDDEN / 4, nullptr);

    // 2) h1 = prelu(x) @ W_enc^T  (fp32 out)
    gemm_mma<0><<<dim3(HIDDEN / 128, MB), 256, SMEM_SZ>>>(
        xhi, xlo, Wehi, Welo, nullptr, h1, nullptr, nullptr, NNODES, HIDDEN, HIDDEN);

    // 3) zero masked rows
    mask_zero<<<2000, 64>>>(h1, mask);

    // 4) aggr = h1 + E1[4] + E2[0]
    init_aggr<<<(NNODES * (HIDDEN / 4) + 255) / 256, 256>>>(h1, E1, E2, aggr);

    // 5) aggr[dst] += h1[src] + E1[a0] + E2[a1]
    edge_scatter<<<(NEDGES + 7) / 8, 256>>>(h1, ei, ea, E1, E2, aggr);

    // 6) split aggr -> bf16 hi/lo
    split_f32<0><<<(NNODES * HIDDEN / 4 + 255) / 256, 256>>>(aggr, aghi, aglo, NNODES * HIDDEN / 4, nullptr);

    // 7) h2 = relu(aggr @ W1^T + b1) -> bf16 hi/lo
    gemm_mma<1><<<dim3(2 * HIDDEN / 128, MB), 256, SMEM_SZ>>>(
        aghi, aglo, W1hi, W1lo, b1, nullptr, h2hi, h2lo, NNODES, 2 * HIDDEN, HIDDEN);

    // 8) out = h2 @ W2^T + b2 (fp32)
    gemm_mma<2><<<dim3(HIDDEN / 128, MB), 256, SMEM_SZ>>>(
        h2hi, h2lo, W2hi, W2lo, b2, out, nullptr, nullptr, NNODES, HIDDEN, 2 * HIDDEN);
}

// round 11
// speedup vs baseline: 1.8990x; 1.0741x over previous
#include <cuda_runtime.h>
#include <cuda_bf16.h>
#include <cstdint>

#define HIDDEN 256
#define NNODES 20000
#define NEDGES 320000

typedef unsigned long long u64;

// ---------------- device global scratch (allocation-free rule) ----------------
__device__ __align__(16) float g_h1[NNODES * HIDDEN];     // enc output (fp32)
__device__ __align__(16) __nv_bfloat16 g_x_hi[NNODES * HIDDEN];
__device__ __align__(16) __nv_bfloat16 g_x_lo[NNODES * HIDDEN];
__device__ __align__(16) __nv_bfloat16 g_ag_hi[NNODES * HIDDEN];
__device__ __align__(16) __nv_bfloat16 g_ag_lo[NNODES * HIDDEN];
__device__ __align__(16) __nv_bfloat16 g_h2_hi[NNODES * 2 * HIDDEN];
__device__ __align__(16) __nv_bfloat16 g_h2_lo[NNODES * 2 * HIDDEN];
__device__ __align__(16) __nv_bfloat16 g_We_hi[HIDDEN * HIDDEN];
__device__ __align__(16) __nv_bfloat16 g_We_lo[HIDDEN * HIDDEN];
__device__ __align__(16) __nv_bfloat16 g_W1_hi[2 * HIDDEN * HIDDEN];
__device__ __align__(16) __nv_bfloat16 g_W1_lo[2 * HIDDEN * HIDDEN];
__device__ __align__(16) __nv_bfloat16 g_W2_hi[HIDDEN * 2 * HIDDEN];
__device__ __align__(16) __nv_bfloat16 g_W2_lo[HIDDEN * 2 * HIDDEN];
// sort/aggregate scratch
__device__ int  g_deg[NNODES];
__device__ int  g_cnt[NNODES];
__device__ int  g_off[NNODES];
__device__ __align__(16) int2  g_sorted[NEDGES];          // (src, combo)
__device__ __align__(16) float g_Ctab[10 * HIDDEN];       // 9 combos + selfloop
__device__ int g_is64;

// ---------------- index dtype probe ----------------
__global__ void detect_idx_dtype(const int* __restrict__ ei_words)
{
    int is64 = 1;
    for (int i = 1; i < 64; i += 2)
        if (ei_words[i] != 0) { is64 = 0; break; }
    g_is64 = is64;
}
__device__ __forceinline__ long long load_idx(const void* p, long long i, int is64)
{
    return is64 ? ((const long long*)p)[i] : (long long)((const int*)p)[i];
}

__device__ __forceinline__ uint32_t smem_u32(const void* p) {
    uint32_t a;
    asm("{ .reg .u64 t; cvta.to.shared.u64 t, %1; cvt.u32.u64 %0, t; }"
        : "=r"(a) : "l"(p));
    return a;
}

// cp.async 16B with zero-fill predicate (src-size=0 -> fill zeros)
__device__ __forceinline__ void cp16(uint32_t dst, const void* src, bool pred) {
    int sz = pred ? 16 : 0;
    asm volatile("cp.async.cg.shared.global [%0], [%1], 16, %2;"
                 :: "r"(dst), "l"(src), "r"(sz) : "memory");
}
#define CP_COMMIT() asm volatile("cp.async.commit_group;" ::: "memory")
#define CP_WAIT(n)  asm volatile("cp.async.wait_group %0;" :: "n"(n) : "memory")

// SW128-style swizzle inside an 8KB tile:
__device__ __forceinline__ uint32_t tile_off(int r, int c) {
    uint32_t off = (uint32_t)((r & 63) * 128 + ((r >> 6) << 6) + c);
    return off ^ ((off >> 3) & 0x70);
}

// ---------------- hi/lo split ----------------
__device__ __forceinline__ void split1(float v, __nv_bfloat16& h, __nv_bfloat16& l) {
    h = __float2bfloat16(v);
    l = __float2bfloat16(v - __bfloat162float(h));
}

template <int PRELU>
__global__ __launch_bounds__(256)
void split_f32(const float* __restrict__ in, __nv_bfloat16* __restrict__ hi,
               __nv_bfloat16* __restrict__ lo, int n4, const float* __restrict__ pa)
{
    int i = blockIdx.x * 256 + threadIdx.x;
    if (i >= n4) return;
    float4 v = ((const float4*)in)[i];
    if (PRELU) {
        float a = *pa;
        v.x = v.x >= 0.f ? v.x : a * v.x;
        v.y = v.y >= 0.f ? v.y : a * v.y;
        v.z = v.z >= 0.f ? v.z : a * v.z;
        v.w = v.w >= 0.f ? v.w : a * v.w;
    }
    __nv_bfloat16 h[4], l[4];
    split1(v.x, h[0], l[0]); split1(v.y, h[1], l[1]);
    split1(v.z, h[2], l[2]); split1(v.w, h[3], l[3]);
    ((uint2*)hi)[i] = *(uint2*)h;
    ((uint2*)lo)[i] = *(uint2*)l;
}

// ---------------- mma.sync helpers ----------------
__device__ __forceinline__ void ldmat4(uint32_t& r0, uint32_t& r1, uint32_t& r2,
                                       uint32_t& r3, uint32_t addr) {
    asm volatile("ldmatrix.sync.aligned.m8n8.x4.shared.b16 {%0,%1,%2,%3}, [%4];"
                 : "=r"(r0), "=r"(r1), "=r"(r2), "=r"(r3) : "r"(addr));
}
__device__ __forceinline__ void mma16816(float& d0, float& d1, float& d2, float& d3,
                                         uint32_t a0, uint32_t a1, uint32_t a2, uint32_t a3,
                                         uint32_t b0, uint32_t b1) {
    asm volatile("mma.sync.aligned.m16n8k16.row.col.f32.bf16.bf16.f32 "
                 "{%0,%1,%2,%3}, {%4,%5,%6,%7}, {%8,%9}, {%0,%1,%2,%3};"
                 : "+f"(d0), "+f"(d1), "+f"(d2), "+f"(d3)
                 : "r"(a0), "r"(a1), "r"(a2), "r"(a3), "r"(b0), "r"(b1));
}

// ---------------------------------------------------------------------------
// bf16 hi/lo GEMM (unchanged from round 10; cp.async double-buffered, swizzled)
// ---------------------------------------------------------------------------
#define TILE_B 8192
#define STG_B  (4 * TILE_B)

template <int MODE>
__global__ __launch_bounds__(256)
void gemm_mma(const __nv_bfloat16* __restrict__ Ahi, const __nv_bfloat16* __restrict__ Alo,
              const __nv_bfloat16* __restrict__ Bhi, const __nv_bfloat16* __restrict__ Blo,
              const float* __restrict__ bias, float* __restrict__ Cf,
              __nv_bfloat16* __restrict__ Chi, __nv_bfloat16* __restrict__ Clo,
              int M, int N, int K)
{
    extern __shared__ __align__(1024) char smem[];
    const uint32_t sb = smem_u32(smem);

    const int tid = threadIdx.x, lane = tid & 31, wid = tid >> 5;
    const int wm = wid >> 2, wn = wid & 3;
    const int m0 = blockIdx.y * 128, n0 = blockIdx.x * 128;

    const int ra = lane & 7, mata = lane >> 3;
    const int aRow = ra + (mata & 1) * 8, aCol = (mata >> 1) * 8;

    float d[4][4][4];
#pragma unroll
    for (int i = 0; i < 4; i++)
#pragma unroll
        for (int j = 0; j < 4; j++)
#pragma unroll
            for (int k = 0; k < 4; k++) d[i][j][k] = 0.f;

    const int nchunks = K >> 5;

    auto load_stage = [&](int c, int buf) {
        const int k0c = c << 5;
        const uint32_t st = sb + buf * STG_B;
#pragma unroll
        for (int i = 0; i < 8; i++) {
            int q = tid + 256 * i;
            int tile = q >> 9;
            int rem = q & 511;
            int r = rem >> 2, seg = rem & 3;
            uint32_t dst = st + tile * TILE_B + tile_off(r, seg * 16);
            if (tile < 2) {
                int row = m0 + r;
                bool ok = row < M;
                const __nv_bfloat16* src =
                    (tile ? Alo : Ahi) + (size_t)(ok ? row : 0) * K + k0c + seg * 8;
                cp16(dst, src, ok);
            } else {
                const __nv_bfloat16* src =
                    (tile == 3 ? Blo : Bhi) + (size_t)(n0 + r) * K + k0c + seg * 8;
                cp16(dst, src, true);
            }
        }
        CP_COMMIT();
    };

    load_stage(0, 0);

    for (int c = 0; c < nchunks; c++) {
        if (c + 1 < nchunks) load_stage(c + 1, (c + 1) & 1);
        if (c + 1 < nchunks) { CP_WAIT(1); } else { CP_WAIT(0); }
        __syncthreads();

        const uint32_t st = sb + (c & 1) * STG_B;
        const uint32_t sAhi = st, sAlo = st + TILE_B;
        const uint32_t sBhi = st + 2 * TILE_B, sBlo = st + 3 * TILE_B;

#pragma unroll
        for (int ks = 0; ks < 2; ks++) {
            const int kk = ks * 16;
            const int cb = (kk + aCol) * 2;

            uint32_t a[4][4];
#pragma unroll
            for (int mf = 0; mf < 4; mf++)
                ldmat4(a[mf][0], a[mf][1], a[mf][2], a[mf][3],
                       sAhi + tile_off(wm * 64 + mf * 16 + aRow, cb));
            uint32_t bh[2][4], bl[2][4];
#pragma unroll
            for (int bf = 0; bf < 2; bf++) {
                ldmat4(bh[bf][0], bh[bf][1], bh[bf][2], bh[bf][3],
                       sBhi + tile_off(wn * 32 + bf * 16 + aRow, cb));
                ldmat4(bl[bf][0], bl[bf][1], bl[bf][2], bl[bf][3],
                       sBlo + tile_off(wn * 32 + bf * 16 + aRow, cb));
            }
#pragma unroll
            for (int mf = 0; mf < 4; mf++)
#pragma unroll
                for (int nf = 0; nf < 4; nf++) {
                    mma16816(d[mf][nf][0], d[mf][nf][1], d[mf][nf][2], d[mf][nf][3],
                             a[mf][0], a[mf][1], a[mf][2], a[mf][3],
                             bh[nf >> 1][(nf & 1)], bh[nf >> 1][(nf & 1) + 2]);
                    mma16816(d[mf][nf][0], d[mf][nf][1], d[mf][nf][2], d[mf][nf][3],
                             a[mf][0], a[mf][1], a[mf][2], a[mf][3],
                             bl[nf >> 1][(nf & 1)], bl[nf >> 1][(nf & 1) + 2]);
                }
#pragma unroll
            for (int mf = 0; mf < 4; mf++)
                ldmat4(a[mf][0], a[mf][1], a[mf][2], a[mf][3],
                       sAlo + tile_off(wm * 64 + mf * 16 + aRow, cb));
#pragma unroll
            for (int mf = 0; mf < 4; mf++)
#pragma unroll
                for (int nf = 0; nf < 4; nf++)
                    mma16816(d[mf][nf][0], d[mf][nf][1], d[mf][nf][2], d[mf][nf][3],
                             a[mf][0], a[mf][1], a[mf][2], a[mf][3],
                             bh[nf >> 1][(nf & 1)], bh[nf >> 1][(nf & 1) + 2]);
        }
        __syncthreads();
    }

#pragma unroll
    for (int mf = 0; mf < 4; mf++) {
        int row = m0 + wm * 64 + mf * 16 + (lane >> 2);
#pragma unroll
        for (int half = 0; half < 2; half++) {
            int r = row + half * 8;
            if (r >= M) continue;
#pragma unroll
            for (int nf = 0; nf < 4; nf++) {
                int col = n0 + wn * 32 + nf * 8 + (lane & 3) * 2;
                float v0 = d[mf][nf][half * 2], v1 = d[mf][nf][half * 2 + 1];
                if (MODE >= 1) {
                    v0 += __ldg(bias + col);
                    v1 += __ldg(bias + col + 1);
                }
                if (MODE == 1) {
                    v0 = fmaxf(v0, 0.f); v1 = fmaxf(v1, 0.f);
                    __nv_bfloat16 h0, l0, h1, l1;
                    split1(v0, h0, l0); split1(v1, h1, l1);
                    __nv_bfloat162 hh; hh.x = h0; hh.y = h1;
                    __nv_bfloat162 ll; ll.x = l0; ll.y = l1;
                    *(__nv_bfloat162*)(Chi + (size_t)r * N + col) = hh;
                    *(__nv_bfloat162*)(Clo + (size_t)r * N + col) = ll;
                } else {
                    *(float2*)(Cf + (size_t)r * N + col) = make_float2(v0, v1);
                }
            }
        }
    }
}

// ---------------- graph part: sorted aggregation ----------------
__global__ void mask_zero(float* __restrict__ h, const void* __restrict__ idx)
{
    long long r = load_idx(idx, blockIdx.x, g_is64);
    ((float4*)(h + r * HIDDEN))[threadIdx.x] = make_float4(0.f, 0.f, 0.f, 0.f);
}

__global__ void zero_counters(int* __restrict__ deg, int* __restrict__ cnt)
{
    int i = blockIdx.x * 256 + threadIdx.x;
    if (i < NNODES) { deg[i] = 0; cnt[i] = 0; }
}

__global__ void hist_dst(const void* __restrict__ ei, int* __restrict__ deg)
{
    int e = blockIdx.x * 256 + threadIdx.x;
    if (e >= NEDGES) return;
    int dst = (int)load_idx(ei, (long long)NEDGES + e, g_is64);
    atomicAdd(&deg[dst], 1);
}

// Exclusive prefix scan over NNODES (single block, 1024 threads, 20/thread)
__global__ __launch_bounds__(1024)
void scan_deg(const int* __restrict__ deg, int* __restrict__ off)
{
    __shared__ int s[1024];
    const int t = threadIdx.x;
    const int base = t * 20;
    int local[20];
    int sum = 0;
#pragma unroll
    for (int i = 0; i < 20; i++) {
        int idx = base + i;
        int v = (idx < NNODES) ? deg[idx] : 0;
        local[i] = sum;
        sum += v;
    }
    s[t] = sum;
    __syncthreads();
    for (int d = 1; d < 1024; d <<= 1) {
        int v = (t >= d) ? s[t - d] : 0;
        __syncthreads();
        s[t] += v;
        __syncthreads();
    }
    int pre = (t == 0) ? 0 : s[t - 1];
#pragma unroll
    for (int i = 0; i < 20; i++) {
        int idx = base + i;
        if (idx < NNODES) off[idx] = pre + local[i];
    }
}

__global__ void scatter_edges(const void* __restrict__ ei, const void* __restrict__ ea,
                              const int* __restrict__ off, int* __restrict__ cnt,
                              int2* __restrict__ sorted)
{
    int e = blockIdx.x * 256 + threadIdx.x;
    if (e >= NEDGES) return;
    const int is64 = g_is64;
    int src = (int)load_idx(ei, e, is64);
    int dst = (int)load_idx(ei, (long long)NEDGES + e, is64);
    int a0  = (int)load_idx(ea, 2LL * e, is64);
    int a1  = (int)load_idx(ea, 2LL * e + 1, is64);
    int pos = off[dst] + atomicAdd(&cnt[dst], 1);
    sorted[pos] = make_int2(src, a0 + 3 * a1);
}

// Ctab[c] = E1[c%3] + E2[c/3] for c in 0..8 ; Ctab[9] = E1[4] + E2[0] (self loop)
__global__ void build_ctab(const float* __restrict__ E1, const float* __restrict__ E2,
                           float* __restrict__ Ctab)
{
    int i = blockIdx.x * 256 + threadIdx.x;   // over 10*HIDDEN
    if (i >= 10 * HIDDEN) return;
    int c = i / HIDDEN, d = i % HIDDEN;
    int r1 = (c == 9) ? 4 : (c % 3);
    int r2 = (c == 9) ? 0 : (c / 3);
    Ctab[i] = E1[r1 * HIDDEN + d] + E2[r2 * HIDDEN + d];
}

// One 64-thread block per node: register accumulation + fused bf16 hi/lo split
__global__ __launch_bounds__(64)
void aggregate(const float* __restrict__ h1, const int2* __restrict__ sorted,
               const int* __restrict__ off, const float* __restrict__ Ctab,
               __nv_bfloat16* __restrict__ aghi, __nv_bfloat16* __restrict__ aglo)
{
    const int n = blockIdx.x;
    const int t = threadIdx.x;     // 0..63 -> float4 column
    const int s0 = off[n];
    const int s1 = (n == NNODES - 1) ? NEDGES : off[n + 1];

    // init with self-loop: h1[n] + E1[4] + E2[0]
    float4 acc = ((const float4*)(h1 + (size_t)n * HIDDEN))[t];
    float4 cs  = ((const float4*)(Ctab + 9 * HIDDEN))[t];
    acc.x += cs.x; acc.y += cs.y; acc.z += cs.z; acc.w += cs.w;

    for (int p = s0; p < s1; p++) {
        int2 rec = __ldg(&sorted[p]);
        float4 xv = ((const float4*)(h1 + (size_t)rec.x * HIDDEN))[t];
        float4 cv = ((const float4*)(Ctab + rec.y * HIDDEN))[t];
        acc.x += xv.x + cv.x;
        acc.y += xv.y + cv.y;
        acc.z += xv.z + cv.z;
        acc.w += xv.w + cv.w;
    }

    __nv_bfloat16 h[4], l[4];
    split1(acc.x, h[0], l[0]); split1(acc.y, h[1], l[1]);
    split1(acc.z, h[2], l[2]); split1(acc.w, h[3], l[3]);
    ((uint2*)(aghi + (size_t)n * HIDDEN))[t] = *(uint2*)h;
    ((uint2*)(aglo + (size_t)n * HIDDEN))[t] = *(uint2*)l;
}

extern "C" void kernel_launch(void* const* d_in, const int* in_sizes, int n_in,
                              void* d_out, int out_size)
{
    const float* x     = (const float*)d_in[0];
    const void*  ei    = d_in[1];
    const void*  ea    = d_in[2];
    const void*  mask  = d_in[3];
    const float* pa    = (const float*)d_in[4];
    const float* W_enc = (const float*)d_in[5];
    const float* E1    = (const float*)d_in[6];
    const float* E2    = (const float*)d_in[7];
    const float* W1    = (const float*)d_in[8];
    const float* b1    = (const float*)d_in[9];
    const float* W2    = (const float*)d_in[10];
    const float* b2    = (const float*)d_in[11];
    float* out = (float*)d_out;

    float *h1, *Ctab;
    int *deg, *cnt, *off;
    int2 *sorted;
    __nv_bfloat16 *xhi, *xlo, *aghi, *aglo, *h2hi, *h2lo;
    __nv_bfloat16 *Wehi, *Welo, *W1hi, *W1lo, *W2hi, *W2lo;
    cudaGetSymbolAddress((void**)&h1,     g_h1);
    cudaGetSymbolAddress((void**)&Ctab,   g_Ctab);
    cudaGetSymbolAddress((void**)&deg,    g_deg);
    cudaGetSymbolAddress((void**)&cnt,    g_cnt);
    cudaGetSymbolAddress((void**)&off,    g_off);
    cudaGetSymbolAddress((void**)&sorted, g_sorted);
    cudaGetSymbolAddress((void**)&xhi,  g_x_hi);
    cudaGetSymbolAddress((void**)&xlo,  g_x_lo);
    cudaGetSymbolAddress((void**)&aghi, g_ag_hi);
    cudaGetSymbolAddress((void**)&aglo, g_ag_lo);
    cudaGetSymbolAddress((void**)&h2hi, g_h2_hi);
    cudaGetSymbolAddress((void**)&h2lo, g_h2_lo);
    cudaGetSymbolAddress((void**)&Wehi, g_We_hi);
    cudaGetSymbolAddress((void**)&Welo, g_We_lo);
    cudaGetSymbolAddress((void**)&W1hi, g_W1_hi);
    cudaGetSymbolAddress((void**)&W1lo, g_W1_lo);
    cudaGetSymbolAddress((void**)&W2hi, g_W2_hi);
    cudaGetSymbolAddress((void**)&W2lo, g_W2_lo);

    const int SMEM_SZ = 2 * STG_B;   // 65536
    cudaFuncSetAttribute(gemm_mma<0>, cudaFuncAttributeMaxDynamicSharedMemorySize, SMEM_SZ);
    cudaFuncSetAttribute(gemm_mma<1>, cudaFuncAttributeMaxDynamicSharedMemorySize, SMEM_SZ);
    cudaFuncSetAttribute(gemm_mma<2>, cudaFuncAttributeMaxDynamicSharedMemorySize, SMEM_SZ);

    const int MB = (NNODES + 127) / 128;   // 157
    const int EB = (NEDGES + 255) / 256;   // 1250

    // 0) index dtype probe + sort prep (independent of GEMM1)
    detect_idx_dtype<<<1, 1>>>((const int*)ei);
    zero_counters<<<(NNODES + 255) / 256, 256>>>(deg, cnt);
    hist_dst<<<EB, 256>>>(ei, deg);
    scan_deg<<<1, 1024>>>(deg, off);
    scatter_edges<<<EB, 256>>>(ei, ea, off, cnt, sorted);
    build_ctab<<<(10 * HIDDEN + 255) / 256, 256>>>(E1, E2, Ctab);

    // 1) splits: x (with PReLU) + weights
    split_f32<1><<<(NNODES * HIDDEN / 4 + 255) / 256, 256>>>(x, xhi, xlo, NNODES * HIDDEN / 4, pa);
    split_f32<0><<<(HIDDEN * HIDDEN / 4 + 255) / 256, 256>>>(W_enc, Wehi, Welo, HIDDEN * HIDDEN / 4, nullptr);
    split_f32<0><<<(2 * HIDDEN * HIDDEN / 4 + 255) / 256, 256>>>(W1, W1hi, W1lo, 2 * HIDDEN * HIDDEN / 4, nullptr);
    split_f32<0><<<(2 * HIDDEN * HIDDEN / 4 + 255) / 256, 256>>>(W2, W2hi, W2lo, 2 * HIDDEN * HIDDEN / 4, nullptr);

    // 2) h1 = prelu(x) @ W_enc^T  (fp32 out)
    gemm_mma<0><<<dim3(HIDDEN / 128, MB), 256, SMEM_SZ>>>(
        xhi, xlo, Wehi, Welo, nullptr, h1, nullptr, nullptr, NNODES, HIDDEN, HIDDEN);

    // 3) zero masked rows
    mask_zero<<<2000, 64>>>(h1, mask);

    // 4) sorted segment-sum + self loops + fused bf16 split
    aggregate<<<NNODES, 64>>>(h1, sorted, off, Ctab, aghi, aglo);

    // 5) h2 = relu(aggr @ W1^T + b1) -> bf16 hi/lo
    gemm_mma<1><<<dim3(2 * HIDDEN / 128, MB), 256, SMEM_SZ>>>(
        aghi, aglo, W1hi, W1lo, b1, nullptr, h2hi, h2lo, NNODES, 2 * HIDDEN, HIDDEN);

    // 6) out = h2 @ W2^T + b2 (fp32)
    gemm_mma<2><<<dim3(HIDDEN / 128, MB), 256, SMEM_SZ>>>(
        h2hi, h2lo, W2hi, W2lo, b2, out, nullptr, nullptr, NNODES, HIDDEN, 2 * HIDDEN);
}

// round 13
// speedup vs baseline: 1.9873x; 1.0465x over previous
#include <cuda_runtime.h>
#include <cuda_bf16.h>
#include <cstdint>

#define HIDDEN 256
#define NNODES 20000
#define NEDGES 320000

typedef unsigned long long u64;

// ---------------- device global scratch (allocation-free rule) ----------------
__device__ __align__(16) float g_h1[NNODES * HIDDEN];     // enc output (fp32)
__device__ __align__(16) __nv_bfloat16 g_x_hi[NNODES * HIDDEN];
__device__ __align__(16) __nv_bfloat16 g_x_lo[NNODES * HIDDEN];
__device__ __align__(16) __nv_bfloat16 g_ag_hi[NNODES * HIDDEN];
__device__ __align__(16) __nv_bfloat16 g_ag_lo[NNODES * HIDDEN];
__device__ __align__(16) __nv_bfloat16 g_h2_hi[NNODES * 2 * HIDDEN];
__device__ __align__(16) __nv_bfloat16 g_h2_lo[NNODES * 2 * HIDDEN];
__device__ __align__(16) __nv_bfloat16 g_We_hi[HIDDEN * HIDDEN];
__device__ __align__(16) __nv_bfloat16 g_We_lo[HIDDEN * HIDDEN];
__device__ __align__(16) __nv_bfloat16 g_W1_hi[2 * HIDDEN * HIDDEN];
__device__ __align__(16) __nv_bfloat16 g_W1_lo[2 * HIDDEN * HIDDEN];
__device__ __align__(16) __nv_bfloat16 g_W2_hi[HIDDEN * 2 * HIDDEN];
__device__ __align__(16) __nv_bfloat16 g_W2_lo[HIDDEN * 2 * HIDDEN];
// sort/aggregate scratch
__device__ __align__(16) int  g_deg[NNODES];
__device__ __align__(16) int  g_cnt[NNODES];
__device__ __align__(16) int  g_off[NNODES];
__device__ __align__(16) int2  g_sorted[NEDGES];          // (src, combo)
__device__ __align__(16) float g_Ctab[10 * HIDDEN];       // 9 combos + selfloop
__device__ int g_is64;

// ---------------- index dtype probe ----------------
__global__ void detect_idx_dtype(const int* __restrict__ ei_words)
{
    int is64 = 1;
    for (int i = 1; i < 64; i += 2)
        if (ei_words[i] != 0) { is64 = 0; break; }
    g_is64 = is64;
}
__device__ __forceinline__ long long load_idx(const void* p, long long i, int is64)
{
    return is64 ? ((const long long*)p)[i] : (long long)((const int*)p)[i];
}

__device__ __forceinline__ uint32_t smem_u32(const void* p) {
    uint32_t a;
    asm("{ .reg .u64 t; cvta.to.shared.u64 t, %1; cvt.u32.u64 %0, t; }"
        : "=r"(a) : "l"(p));
    return a;
}

// cp.async 16B with zero-fill predicate (src-size=0 -> fill zeros)
__device__ __forceinline__ void cp16(uint32_t dst, const void* src, bool pred) {
    int sz = pred ? 16 : 0;
    asm volatile("cp.async.cg.shared.global [%0], [%1], 16, %2;"
                 :: "r"(dst), "l"(src), "r"(sz) : "memory");
}
#define CP_COMMIT() asm volatile("cp.async.commit_group;" ::: "memory")
#define CP_WAIT(n)  asm volatile("cp.async.wait_group %0;" :: "n"(n) : "memory")

// SW128-style swizzle inside an 8KB tile:
__device__ __forceinline__ uint32_t tile_off(int r, int c) {
    uint32_t off = (uint32_t)((r & 63) * 128 + ((r >> 6) << 6) + c);
    return off ^ ((off >> 3) & 0x70);
}

// ---------------- hi/lo split ----------------
__device__ __forceinline__ void split1(float v, __nv_bfloat16& h, __nv_bfloat16& l) {
    h = __float2bfloat16(v);
    l = __float2bfloat16(v - __bfloat162float(h));
}

template <int PRELU>
__global__ __launch_bounds__(256)
void split_f32(const float* __restrict__ in, __nv_bfloat16* __restrict__ hi,
               __nv_bfloat16* __restrict__ lo, int n4, const float* __restrict__ pa)
{
    int i = blockIdx.x * 256 + threadIdx.x;
    if (i >= n4) return;
    float4 v = ((const float4*)in)[i];
    if (PRELU) {
        float a = *pa;
        v.x = v.x >= 0.f ? v.x : a * v.x;
        v.y = v.y >= 0.f ? v.y : a * v.y;
        v.z = v.z >= 0.f ? v.z : a * v.z;
        v.w = v.w >= 0.f ? v.w : a * v.w;
    }
    __nv_bfloat16 h[4], l[4];
    split1(v.x, h[0], l[0]); split1(v.y, h[1], l[1]);
    split1(v.z, h[2], l[2]); split1(v.w, h[3], l[3]);
    ((uint2*)hi)[i] = *(uint2*)h;
    ((uint2*)lo)[i] = *(uint2*)l;
}

// Combined split of the 3 weight matrices (one launch).
// Layout (in float4 units): We 16384 | W1 32768 | W2 32768  = 81920 total
__global__ __launch_bounds__(256)
void split_weights(const float* __restrict__ We, const float* __restrict__ W1,
                   const float* __restrict__ W2,
                   __nv_bfloat16* __restrict__ Wehi, __nv_bfloat16* __restrict__ Welo,
                   __nv_bfloat16* __restrict__ W1hi, __nv_bfloat16* __restrict__ W1lo,
                   __nv_bfloat16* __restrict__ W2hi, __nv_bfloat16* __restrict__ W2lo)
{
    int i = blockIdx.x * 256 + threadIdx.x;
    if (i >= 81920) return;
    const float* in; __nv_bfloat16 *hi, *lo; int j;
    if (i < 16384)      { in = We; hi = Wehi; lo = Welo; j = i; }
    else if (i < 49152) { in = W1; hi = W1hi; lo = W1lo; j = i - 16384; }
    else                { in = W2; hi = W2hi; lo = W2lo; j = i - 49152; }
    float4 v = ((const float4*)in)[j];
    __nv_bfloat16 h[4], l[4];
    split1(v.x, h[0], l[0]); split1(v.y, h[1], l[1]);
    split1(v.z, h[2], l[2]); split1(v.w, h[3], l[3]);
    ((uint2*)hi)[j] = *(uint2*)h;
    ((uint2*)lo)[j] = *(uint2*)l;
}

// ---------------- mma.sync helpers ----------------
__device__ __forceinline__ void ldmat4(uint32_t& r0, uint32_t& r1, uint32_t& r2,
                                       uint32_t& r3, uint32_t addr) {
    asm volatile("ldmatrix.sync.aligned.m8n8.x4.shared.b16 {%0,%1,%2,%3}, [%4];"
                 : "=r"(r0), "=r"(r1), "=r"(r2), "=r"(r3) : "r"(addr));
}
__device__ __forceinline__ void mma16816(float& d0, float& d1, float& d2, float& d3,
                                         uint32_t a0, uint32_t a1, uint32_t a2, uint32_t a3,
                                         uint32_t b0, uint32_t b1) {
    asm volatile("mma.sync.aligned.m16n8k16.row.col.f32.bf16.bf16.f32 "
                 "{%0,%1,%2,%3}, {%4,%5,%6,%7}, {%8,%9}, {%0,%1,%2,%3};"
                 : "+f"(d0), "+f"(d1), "+f"(d2), "+f"(d3)
                 : "r"(a0), "r"(a1), "r"(a2), "r"(a3), "r"(b0), "r"(b1));
}

// ---------------------------------------------------------------------------
// bf16 hi/lo GEMM (cp.async double-buffered, swizzled smem)
// ---------------------------------------------------------------------------
#define TILE_B 8192
#define STG_B  (4 * TILE_B)

template <int MODE>
__global__ __launch_bounds__(256)
void gemm_mma(const __nv_bfloat16* __restrict__ Ahi, const __nv_bfloat16* __restrict__ Alo,
              const __nv_bfloat16* __restrict__ Bhi, const __nv_bfloat16* __restrict__ Blo,
              const float* __restrict__ bias, float* __restrict__ Cf,
              __nv_bfloat16* __restrict__ Chi, __nv_bfloat16* __restrict__ Clo,
              int M, int N, int K)
{
    extern __shared__ __align__(1024) char smem[];
    const uint32_t sb = smem_u32(smem);

    const int tid = threadIdx.x, lane = tid & 31, wid = tid >> 5;
    const int wm = wid >> 2, wn = wid & 3;
    const int m0 = blockIdx.y * 128, n0 = blockIdx.x * 128;

    const int ra = lane & 7, mata = lane >> 3;
    const int aRow = ra + (mata & 1) * 8, aCol = (mata >> 1) * 8;

    float d[4][4][4];
#pragma unroll
    for (int i = 0; i < 4; i++)
#pragma unroll
        for (int j = 0; j < 4; j++)
#pragma unroll
            for (int k = 0; k < 4; k++) d[i][j][k] = 0.f;

    const int nchunks = K >> 5;

    auto load_stage = [&](int c, int buf) {
        const int k0c = c << 5;
        const uint32_t st = sb + buf * STG_B;
#pragma unroll
        for (int i = 0; i < 8; i++) {
            int q = tid + 256 * i;
            int tile = q >> 9;
            int rem = q & 511;
            int r = rem >> 2, seg = rem & 3;
            uint32_t dst = st + tile * TILE_B + tile_off(r, seg * 16);
            if (tile < 2) {
                int row = m0 + r;
                bool ok = row < M;
                const __nv_bfloat16* src =
                    (tile ? Alo : Ahi) + (size_t)(ok ? row : 0) * K + k0c + seg * 8;
                cp16(dst, src, ok);
            } else {
                const __nv_bfloat16* src =
                    (tile == 3 ? Blo : Bhi) + (size_t)(n0 + r) * K + k0c + seg * 8;
                cp16(dst, src, true);
            }
        }
        CP_COMMIT();
    };

    load_stage(0, 0);

    for (int c = 0; c < nchunks; c++) {
        if (c + 1 < nchunks) load_stage(c + 1, (c + 1) & 1);
        if (c + 1 < nchunks) { CP_WAIT(1); } else { CP_WAIT(0); }
        __syncthreads();

        const uint32_t st = sb + (c & 1) * STG_B;
        const uint32_t sAhi = st, sAlo = st + TILE_B;
        const uint32_t sBhi = st + 2 * TILE_B, sBlo = st + 3 * TILE_B;

#pragma unroll
        for (int ks = 0; ks < 2; ks++) {
            const int kk = ks * 16;
            const int cb = (kk + aCol) * 2;

            uint32_t a[4][4];
#pragma unroll
            for (int mf = 0; mf < 4; mf++)
                ldmat4(a[mf][0], a[mf][1], a[mf][2], a[mf][3],
                       sAhi + tile_off(wm * 64 + mf * 16 + aRow, cb));
            uint32_t bh[2][4], bl[2][4];
#pragma unroll
            for (int bf = 0; bf < 2; bf++) {
                ldmat4(bh[bf][0], bh[bf][1], bh[bf][2], bh[bf][3],
                       sBhi + tile_off(wn * 32 + bf * 16 + aRow, cb));
                ldmat4(bl[bf][0], bl[bf][1], bl[bf][2], bl[bf][3],
                       sBlo + tile_off(wn * 32 + bf * 16 + aRow, cb));
            }
#pragma unroll
            for (int mf = 0; mf < 4; mf++)
#pragma unroll
                for (int nf = 0; nf < 4; nf++) {
                    mma16816(d[mf][nf][0], d[mf][nf][1], d[mf][nf][2], d[mf][nf][3],
                             a[mf][0], a[mf][1], a[mf][2], a[mf][3],
                             bh[nf >> 1][(nf & 1)], bh[nf >> 1][(nf & 1) + 2]);
                    mma16816(d[mf][nf][0], d[mf][nf][1], d[mf][nf][2], d[mf][nf][3],
                             a[mf][0], a[mf][1], a[mf][2], a[mf][3],
                             bl[nf >> 1][(nf & 1)], bl[nf >> 1][(nf & 1) + 2]);
                }
#pragma unroll
            for (int mf = 0; mf < 4; mf++)
                ldmat4(a[mf][0], a[mf][1], a[mf][2], a[mf][3],
                       sAlo + tile_off(wm * 64 + mf * 16 + aRow, cb));
#pragma unroll
            for (int mf = 0; mf < 4; mf++)
#pragma unroll
                for (int nf = 0; nf < 4; nf++)
                    mma16816(d[mf][nf][0], d[mf][nf][1], d[mf][nf][2], d[mf][nf][3],
                             a[mf][0], a[mf][1], a[mf][2], a[mf][3],
                             bh[nf >> 1][(nf & 1)], bh[nf >> 1][(nf & 1) + 2]);
        }
        __syncthreads();
    }

#pragma unroll
    for (int mf = 0; mf < 4; mf++) {
        int row = m0 + wm * 64 + mf * 16 + (lane >> 2);
#pragma unroll
        for (int half = 0; half < 2; half++) {
            int r = row + half * 8;
            if (r >= M) continue;
#pragma unroll
            for (int nf = 0; nf < 4; nf++) {
                int col = n0 + wn * 32 + nf * 8 + (lane & 3) * 2;
                float v0 = d[mf][nf][half * 2], v1 = d[mf][nf][half * 2 + 1];
                if (MODE >= 1) {
                    v0 += __ldg(bias + col);
                    v1 += __ldg(bias + col + 1);
                }
                if (MODE == 1) {
                    v0 = fmaxf(v0, 0.f); v1 = fmaxf(v1, 0.f);
                    __nv_bfloat16 h0, l0, h1, l1;
                    split1(v0, h0, l0); split1(v1, h1, l1);
                    __nv_bfloat162 hh; hh.x = h0; hh.y = h1;
                    __nv_bfloat162 ll; ll.x = l0; ll.y = l1;
                    *(__nv_bfloat162*)(Chi + (size_t)r * N + col) = hh;
                    *(__nv_bfloat162*)(Clo + (size_t)r * N + col) = ll;
                } else {
                    *(float2*)(Cf + (size_t)r * N + col) = make_float2(v0, v1);
                }
            }
        }
    }
}

// ---------------- graph part: sorted aggregation ----------------
__global__ void mask_zero(float* __restrict__ h, const void* __restrict__ idx)
{
    long long r = load_idx(idx, blockIdx.x, g_is64);
    ((float4*)(h + r * HIDDEN))[threadIdx.x] = make_float4(0.f, 0.f, 0.f, 0.f);
}

// zero counters + build Ctab in one launch (grid covers NNODES)
__global__ void prep_misc(int* __restrict__ deg, int* __restrict__ cnt,
                          const float* __restrict__ E1, const float* __restrict__ E2,
                          float* __restrict__ Ctab)
{
    int i = blockIdx.x * 256 + threadIdx.x;
    if (i < NNODES) { deg[i] = 0; cnt[i] = 0; }
    if (i < 10 * HIDDEN) {
        int c = i / HIDDEN, dd = i % HIDDEN;
        int r1 = (c == 9) ? 4 : (c % 3);
        int r2 = (c == 9) ? 0 : (c / 3);
        Ctab[i] = E1[r1 * HIDDEN + dd] + E2[r2 * HIDDEN + dd];
    }
}

__global__ void hist_dst(const void* __restrict__ ei, int* __restrict__ deg)
{
    int e = blockIdx.x * 256 + threadIdx.x;
    if (e >= NEDGES) return;
    int dst = (int)load_idx(ei, (long long)NEDGES + e, g_is64);
    atomicAdd(&deg[dst], 1);
}

// Exclusive prefix scan over NNODES ints (= 5000 int4). Single block, 1024 thr.
__global__ __launch_bounds__(1024)
void scan_deg(const int4* __restrict__ deg4, int4* __restrict__ off4)
{
    __shared__ int wsum[32];
    const int t = threadIdx.x, lane = t & 31, w = t >> 5;
    const int base = t * 5;                   // int4 index
    int4 v[5];
    int sum = 0;
#pragma unroll
    for (int i = 0; i < 5; i++) {
        int idx = base + i;
        v[i] = (idx < 5000) ? deg4[idx] : make_int4(0, 0, 0, 0);
        sum += v[i].x + v[i].y + v[i].z + v[i].w;
    }
    // warp inclusive scan of per-thread sums
    int s = sum;
#pragma unroll
    for (int dlt = 1; dlt < 32; dlt <<= 1) {
        int o = __shfl_up_sync(0xffffffff, s, dlt);
        if (lane >= dlt) s += o;
    }
    if (lane == 31) wsum[w] = s;
    __syncthreads();
    if (w == 0) {
        int ws = (t < 32) ? wsum[t] : 0;
#pragma unroll
        for (int dlt = 1; dlt < 32; dlt <<= 1) {
            int o = __shfl_up_sync(0xffffffff, ws, dlt);
            if (lane >= dlt) ws += o;
        }
        if (t < 32) wsum[t] = ws;
    }
    __syncthreads();
    int pre = s - sum + (w > 0 ? wsum[w - 1] : 0);   // exclusive across threads
#pragma unroll
    for (int i = 0; i < 5; i++) {
        int idx = base + i;
        if (idx < 5000) {
            int4 o;
            o.x = pre;            pre += v[i].x;
            o.y = pre;            pre += v[i].y;
            o.z = pre;            pre += v[i].z;
            o.w = pre;            pre += v[i].w;
            off4[idx] = o;
        }
    }
}

__global__ void scatter_edges(const void* __restrict__ ei, const void* __restrict__ ea,
                              const int* __restrict__ off, int* __restrict__ cnt,
                              int2* __restrict__ sorted)
{
    int e = blockIdx.x * 256 + threadIdx.x;
    if (e >= NEDGES) return;
    const int is64 = g_is64;
    int src = (int)load_idx(ei, e, is64);
    int dst = (int)load_idx(ei, (long long)NEDGES + e, is64);
    int a0  = (int)load_idx(ea, 2LL * e, is64);
    int a1  = (int)load_idx(ea, 2LL * e + 1, is64);
    int pos = off[dst] + atomicAdd(&cnt[dst], 1);
    sorted[pos] = make_int2(src, a0 + 3 * a1);
}

// One 64-thread block per node: register accumulation + fused bf16 hi/lo split
__global__ __launch_bounds__(64)
void aggregate(const float* __restrict__ h1, const int2* __restrict__ sorted,
               const int* __restrict__ off, const float* __restrict__ Ctab,
               __nv_bfloat16* __restrict__ aghi, __nv_bfloat16* __restrict__ aglo)
{
    const int n = blockIdx.x;
    const int t = threadIdx.x;     // 0..63 -> float4 column
    const int s0 = off[n];
    const int s1 = (n == NNODES - 1) ? NEDGES : off[n + 1];

    // init with self-loop: h1[n] + E1[4] + E2[0]
    float4 acc = ((const float4*)(h1 + (size_t)n * HIDDEN))[t];
    float4 cs  = ((const float4*)(Ctab + 9 * HIDDEN))[t];
    acc.x += cs.x; acc.y += cs.y; acc.z += cs.z; acc.w += cs.w;

    int p = s0;
    for (; p + 1 < s1; p += 2) {
        int2 r0 = __ldg(&sorted[p]);
        int2 r1 = __ldg(&sorted[p + 1]);
        float4 x0 = ((const float4*)(h1 + (size_t)r0.x * HIDDEN))[t];
        float4 c0 = ((const float4*)(Ctab + r0.y * HIDDEN))[t];
        float4 x1 = ((const float4*)(h1 + (size_t)r1.x * HIDDEN))[t];
        float4 c1 = ((const float4*)(Ctab + r1.y * HIDDEN))[t];
        acc.x += x0.x + c0.x; acc.y += x0.y + c0.y;
        acc.z += x0.z + c0.z; acc.w += x0.w + c0.w;
        acc.x += x1.x + c1.x; acc.y += x1.y + c1.y;
        acc.z += x1.z + c1.z; acc.w += x1.w + c1.w;
    }
    if (p < s1) {
        int2 rec = __ldg(&sorted[p]);
        float4 xv = ((const float4*)(h1 + (size_t)rec.x * HIDDEN))[t];
        float4 cv = ((const float4*)(Ctab + rec.y * HIDDEN))[t];
        acc.x += xv.x + cv.x; acc.y += xv.y + cv.y;
        acc.z += xv.z + cv.z; acc.w += xv.w + cv.w;
    }

    __nv_bfloat16 h[4], l[4];
    split1(acc.x, h[0], l[0]); split1(acc.y, h[1], l[1]);
    split1(acc.z, h[2], l[2]); split1(acc.w, h[3], l[3]);
    ((uint2*)(aghi + (size_t)n * HIDDEN))[t] = *(uint2*)h;
    ((uint2*)(aglo + (size_t)n * HIDDEN))[t] = *(uint2*)l;
}

extern "C" void kernel_launch(void* const* d_in, const int* in_sizes, int n_in,
                              void* d_out, int out_size)
{
    const float* x     = (const float*)d_in[0];
    const void*  ei    = d_in[1];
    const void*  ea    = d_in[2];
    const void*  mask  = d_in[3];
    const float* pa    = (const float*)d_in[4];
    const float* W_enc = (const float*)d_in[5];
    const float* E1    = (const float*)d_in[6];
    const float* E2    = (const float*)d_in[7];
    const float* W1    = (const float*)d_in[8];
    const float* b1    = (const float*)d_in[9];
    const float* W2    = (const float*)d_in[10];
    const float* b2    = (const float*)d_in[11];
    float* out = (float*)d_out;

    float *h1, *Ctab;
    int *deg, *cnt, *off;
    int2 *sorted;
    __nv_bfloat16 *xhi, *xlo, *aghi, *aglo, *h2hi, *h2lo;
    __nv_bfloat16 *Wehi, *Welo, *W1hi, *W1lo, *W2hi, *W2lo;
    cudaGetSymbolAddress((void**)&h1,     g_h1);
    cudaGetSymbolAddress((void**)&Ctab,   g_Ctab);
    cudaGetSymbolAddress((void**)&deg,    g_deg);
    cudaGetSymbolAddress((void**)&cnt,    g_cnt);
    cudaGetSymbolAddress((void**)&off,    g_off);
    cudaGetSymbolAddress((void**)&sorted, g_sorted);
    cudaGetSymbolAddress((void**)&xhi,  g_x_hi);
    cudaGetSymbolAddress((void**)&xlo,  g_x_lo);
    cudaGetSymbolAddress((void**)&aghi, g_ag_hi);
    cudaGetSymbolAddress((void**)&aglo, g_ag_lo);
    cudaGetSymbolAddress((void**)&h2hi, g_h2_hi);
    cudaGetSymbolAddress((void**)&h2lo, g_h2_lo);
    cudaGetSymbolAddress((void**)&Wehi, g_We_hi);
    cudaGetSymbolAddress((void**)&Welo, g_We_lo);
    cudaGetSymbolAddress((void**)&W1hi, g_W1_hi);
    cudaGetSymbolAddress((void**)&W1lo, g_W1_lo);
    cudaGetSymbolAddress((void**)&W2hi, g_W2_hi);
    cudaGetSymbolAddress((void**)&W2lo, g_W2_lo);

    const int SMEM_SZ = 2 * STG_B;   // 65536
    cudaFuncSetAttribute(gemm_mma<0>, cudaFuncAttributeMaxDynamicSharedMemorySize, SMEM_SZ);
    cudaFuncSetAttribute(gemm_mma<1>, cudaFuncAttributeMaxDynamicSharedMemorySize, SMEM_SZ);
    cudaFuncSetAttribute(gemm_mma<2>, cudaFuncAttributeMaxDynamicSharedMemorySize, SMEM_SZ);

    const int MB = (NNODES + 127) / 128;   // 157
    const int EB = (NEDGES + 255) / 256;   // 1250

    // 0) index dtype probe + graph prep
    detect_idx_dtype<<<1, 1>>>((const int*)ei);
    prep_misc<<<(NNODES + 255) / 256, 256>>>(deg, cnt, E1, E2, Ctab);
    hist_dst<<<EB, 256>>>(ei, deg);
    scan_deg<<<1, 1024>>>((const int4*)deg, (int4*)off);
    scatter_edges<<<EB, 256>>>(ei, ea, off, cnt, sorted);

    // 1) splits: x (with PReLU) + all weights in one launch
    split_f32<1><<<(NNODES * HIDDEN / 4 + 255) / 256, 256>>>(x, xhi, xlo, NNODES * HIDDEN / 4, pa);
    split_weights<<<(81920 + 255) / 256, 256>>>(W_enc, W1, W2,
                                                Wehi, Welo, W1hi, W1lo, W2hi, W2lo);

    // 2) h1 = prelu(x) @ W_enc^T  (fp32 out)
    gemm_mma<0><<<dim3(HIDDEN / 128, MB), 256, SMEM_SZ>>>(
        xhi, xlo, Wehi, Welo, nullptr, h1, nullptr, nullptr, NNODES, HIDDEN, HIDDEN);

    // 3) zero masked rows
    mask_zero<<<2000, 64>>>(h1, mask);

    // 4) sorted segment-sum + self loops + fused bf16 split
    aggregate<<<NNODES, 64>>>(h1, sorted, off, Ctab, aghi, aglo);

    // 5) h2 = relu(aggr @ W1^T + b1) -> bf16 hi/lo
    gemm_mma<1><<<dim3(2 * HIDDEN / 128, MB), 256, SMEM_SZ>>>(
        aghi, aglo, W1hi, W1lo, b1, nullptr, h2hi, h2lo, NNODES, 2 * HIDDEN, HIDDEN);

    // 6) out = h2 @ W2^T + b2 (fp32)
    gemm_mma<2><<<dim3(HIDDEN / 128, MB), 256, SMEM_SZ>>>(
        h2hi, h2lo, W2hi, W2lo, b2, out, nullptr, nullptr, NNODES, HIDDEN, 2 * HIDDEN);
}

// round 14
// speedup vs baseline: 2.1118x; 1.0626x over previous
#include <cuda_runtime.h>
#include <cuda_bf16.h>
#include <cstdint>

#define HIDDEN 256
#define NNODES 20000
#define NEDGES 320000

typedef unsigned long long u64;

// ---------------- device global scratch (allocation-free rule) ----------------
__device__ __align__(16) float g_h1[NNODES * HIDDEN];     // enc output (fp32)
__device__ __align__(16) __nv_bfloat16 g_x_hi[NNODES * HIDDEN];
__device__ __align__(16) __nv_bfloat16 g_x_lo[NNODES * HIDDEN];
__device__ __align__(16) __nv_bfloat16 g_ag_hi[NNODES * HIDDEN];
__device__ __align__(16) __nv_bfloat16 g_ag_lo[NNODES * HIDDEN];
__device__ __align__(16) __nv_bfloat16 g_h2_hi[NNODES * 2 * HIDDEN];
__device__ __align__(16) __nv_bfloat16 g_h2_lo[NNODES * 2 * HIDDEN];
__device__ __align__(16) __nv_bfloat16 g_We_hi[HIDDEN * HIDDEN];
__device__ __align__(16) __nv_bfloat16 g_We_lo[HIDDEN * HIDDEN];
__device__ __align__(16) __nv_bfloat16 g_W1_hi[2 * HIDDEN * HIDDEN];
__device__ __align__(16) __nv_bfloat16 g_W1_lo[2 * HIDDEN * HIDDEN];
__device__ __align__(16) __nv_bfloat16 g_W2_hi[HIDDEN * 2 * HIDDEN];
__device__ __align__(16) __nv_bfloat16 g_W2_lo[HIDDEN * 2 * HIDDEN];
// sort/aggregate scratch
__device__ __align__(16) int  g_deg[NNODES];
__device__ __align__(16) int  g_cnt[NNODES];
__device__ __align__(16) int  g_off[NNODES];
__device__ __align__(16) int2  g_sorted[NEDGES];          // (src, combo)
__device__ __align__(16) float g_Ctab[10 * HIDDEN];       // 9 combos + selfloop
__device__ int g_is64;

// ---------------- host-side stream/event infra (created before main) ----------
static cudaStream_t g_s2;
static cudaEvent_t  g_evFork, g_evJoin;
struct GInit {
    GInit() {
        cudaStreamCreateWithFlags(&g_s2, cudaStreamNonBlocking);
        cudaEventCreateWithFlags(&g_evFork, cudaEventDisableTiming);
        cudaEventCreateWithFlags(&g_evJoin, cudaEventDisableTiming);
    }
};
static GInit g_init;

// ---------------- index dtype helpers ----------------
__device__ __forceinline__ long long load_idx(const void* p, long long i, int is64)
{
    return is64 ? ((const long long*)p)[i] : (long long)((const int*)p)[i];
}

__device__ __forceinline__ uint32_t smem_u32(const void* p) {
    uint32_t a;
    asm("{ .reg .u64 t; cvta.to.shared.u64 t, %1; cvt.u32.u64 %0, t; }"
        : "=r"(a) : "l"(p));
    return a;
}

// cp.async 16B with zero-fill predicate (src-size=0 -> fill zeros)
__device__ __forceinline__ void cp16(uint32_t dst, const void* src, bool pred) {
    int sz = pred ? 16 : 0;
    asm volatile("cp.async.cg.shared.global [%0], [%1], 16, %2;"
                 :: "r"(dst), "l"(src), "r"(sz) : "memory");
}
#define CP_COMMIT() asm volatile("cp.async.commit_group;" ::: "memory")
#define CP_WAIT(n)  asm volatile("cp.async.wait_group %0;" :: "n"(n) : "memory")

// SW128-style swizzle inside an 8KB tile:
__device__ __forceinline__ uint32_t tile_off(int r, int c) {
    uint32_t off = (uint32_t)((r & 63) * 128 + ((r >> 6) << 6) + c);
    return off ^ ((off >> 3) & 0x70);
}

// ---------------- hi/lo split ----------------
__device__ __forceinline__ void split1(float v, __nv_bfloat16& h, __nv_bfloat16& l) {
    h = __float2bfloat16(v);
    l = __float2bfloat16(v - __bfloat162float(h));
}

template <int PRELU>
__global__ __launch_bounds__(256)
void split_f32(const float* __restrict__ in, __nv_bfloat16* __restrict__ hi,
               __nv_bfloat16* __restrict__ lo, int n4, const float* __restrict__ pa)
{
    int i = blockIdx.x * 256 + threadIdx.x;
    if (i >= n4) return;
    float4 v = ((const float4*)in)[i];
    if (PRELU) {
        float a = *pa;
        v.x = v.x >= 0.f ? v.x : a * v.x;
        v.y = v.y >= 0.f ? v.y : a * v.y;
        v.z = v.z >= 0.f ? v.z : a * v.z;
        v.w = v.w >= 0.f ? v.w : a * v.w;
    }
    __nv_bfloat16 h[4], l[4];
    split1(v.x, h[0], l[0]); split1(v.y, h[1], l[1]);
    split1(v.z, h[2], l[2]); split1(v.w, h[3], l[3]);
    ((uint2*)hi)[i] = *(uint2*)h;
    ((uint2*)lo)[i] = *(uint2*)l;
}

// Combined split of the 3 weight matrices (one launch).
__global__ __launch_bounds__(256)
void split_weights(const float* __restrict__ We, const float* __restrict__ W1,
                   const float* __restrict__ W2,
                   __nv_bfloat16* __restrict__ Wehi, __nv_bfloat16* __restrict__ Welo,
                   __nv_bfloat16* __restrict__ W1hi, __nv_bfloat16* __restrict__ W1lo,
                   __nv_bfloat16* __restrict__ W2hi, __nv_bfloat16* __restrict__ W2lo)
{
    int i = blockIdx.x * 256 + threadIdx.x;
    if (i >= 81920) return;
    const float* in; __nv_bfloat16 *hi, *lo; int j;
    if (i < 16384)      { in = We; hi = Wehi; lo = Welo; j = i; }
    else if (i < 49152) { in = W1; hi = W1hi; lo = W1lo; j = i - 16384; }
    else                { in = W2; hi = W2hi; lo = W2lo; j = i - 49152; }
    float4 v = ((const float4*)in)[j];
    __nv_bfloat16 h[4], l[4];
    split1(v.x, h[0], l[0]); split1(v.y, h[1], l[1]);
    split1(v.z, h[2], l[2]); split1(v.w, h[3], l[3]);
    ((uint2*)hi)[j] = *(uint2*)h;
    ((uint2*)lo)[j] = *(uint2*)l;
}

// ---------------- mma.sync helpers ----------------
__device__ __forceinline__ void ldmat4(uint32_t& r0, uint32_t& r1, uint32_t& r2,
                                       uint32_t& r3, uint32_t addr) {
    asm volatile("ldmatrix.sync.aligned.m8n8.x4.shared.b16 {%0,%1,%2,%3}, [%4];"
                 : "=r"(r0), "=r"(r1), "=r"(r2), "=r"(r3) : "r"(addr));
}
__device__ __forceinline__ void mma16816(float& d0, float& d1, float& d2, float& d3,
                                         uint32_t a0, uint32_t a1, uint32_t a2, uint32_t a3,
                                         uint32_t b0, uint32_t b1) {
    asm volatile("mma.sync.aligned.m16n8k16.row.col.f32.bf16.bf16.f32 "
                 "{%0,%1,%2,%3}, {%4,%5,%6,%7}, {%8,%9}, {%0,%1,%2,%3};"
                 : "+f"(d0), "+f"(d1), "+f"(d2), "+f"(d3)
                 : "r"(a0), "r"(a1), "r"(a2), "r"(a3), "r"(b0), "r"(b1));
}

// ---------------------------------------------------------------------------
// bf16 hi/lo GEMM (cp.async double-buffered, swizzled smem)
// ---------------------------------------------------------------------------
#define TILE_B 8192
#define STG_B  (4 * TILE_B)

template <int MODE>
__global__ __launch_bounds__(256)
void gemm_mma(const __nv_bfloat16* __restrict__ Ahi, const __nv_bfloat16* __restrict__ Alo,
              const __nv_bfloat16* __restrict__ Bhi, const __nv_bfloat16* __restrict__ Blo,
              const float* __restrict__ bias, float* __restrict__ Cf,
              __nv_bfloat16* __restrict__ Chi, __nv_bfloat16* __restrict__ Clo,
              int M, int N, int K)
{
    extern __shared__ __align__(1024) char smem[];
    const uint32_t sb = smem_u32(smem);

    const int tid = threadIdx.x, lane = tid & 31, wid = tid >> 5;
    const int wm = wid >> 2, wn = wid & 3;
    const int m0 = blockIdx.y * 128, n0 = blockIdx.x * 128;

    const int ra = lane & 7, mata = lane >> 3;
    const int aRow = ra + (mata & 1) * 8, aCol = (mata >> 1) * 8;

    float d[4][4][4];
#pragma unroll
    for (int i = 0; i < 4; i++)
#pragma unroll
        for (int j = 0; j < 4; j++)
#pragma unroll
            for (int k = 0; k < 4; k++) d[i][j][k] = 0.f;

    const int nchunks = K >> 5;

    auto load_stage = [&](int c, int buf) {
        const int k0c = c << 5;
        const uint32_t st = sb + buf * STG_B;
#pragma unroll
        for (int i = 0; i < 8; i++) {
            int q = tid + 256 * i;
            int tile = q >> 9;
            int rem = q & 511;
            int r = rem >> 2, seg = rem & 3;
            uint32_t dst = st + tile * TILE_B + tile_off(r, seg * 16);
            if (tile < 2) {
                int row = m0 + r;
                bool ok = row < M;
                const __nv_bfloat16* src =
                    (tile ? Alo : Ahi) + (size_t)(ok ? row : 0) * K + k0c + seg * 8;
                cp16(dst, src, ok);
            } else {
                const __nv_bfloat16* src =
                    (tile == 3 ? Blo : Bhi) + (size_t)(n0 + r) * K + k0c + seg * 8;
                cp16(dst, src, true);
            }
        }
        CP_COMMIT();
    };

    load_stage(0, 0);

    for (int c = 0; c < nchunks; c++) {
        if (c + 1 < nchunks) load_stage(c + 1, (c + 1) & 1);
        if (c + 1 < nchunks) { CP_WAIT(1); } else { CP_WAIT(0); }
        __syncthreads();

        const uint32_t st = sb + (c & 1) * STG_B;
        const uint32_t sAhi = st, sAlo = st + TILE_B;
        const uint32_t sBhi = st + 2 * TILE_B, sBlo = st + 3 * TILE_B;

#pragma unroll
        for (int ks = 0; ks < 2; ks++) {
            const int kk = ks * 16;
            const int cb = (kk + aCol) * 2;

            uint32_t a[4][4];
#pragma unroll
            for (int mf = 0; mf < 4; mf++)
                ldmat4(a[mf][0], a[mf][1], a[mf][2], a[mf][3],
                       sAhi + tile_off(wm * 64 + mf * 16 + aRow, cb));
            uint32_t bh[2][4], bl[2][4];
#pragma unroll
            for (int bf = 0; bf < 2; bf++) {
                ldmat4(bh[bf][0], bh[bf][1], bh[bf][2], bh[bf][3],
                       sBhi + tile_off(wn * 32 + bf * 16 + aRow, cb));
                ldmat4(bl[bf][0], bl[bf][1], bl[bf][2], bl[bf][3],
                       sBlo + tile_off(wn * 32 + bf * 16 + aRow, cb));
            }
#pragma unroll
            for (int mf = 0; mf < 4; mf++)
#pragma unroll
                for (int nf = 0; nf < 4; nf++) {
                    mma16816(d[mf][nf][0], d[mf][nf][1], d[mf][nf][2], d[mf][nf][3],
                             a[mf][0], a[mf][1], a[mf][2], a[mf][3],
                             bh[nf >> 1][(nf & 1)], bh[nf >> 1][(nf & 1) + 2]);
                    mma16816(d[mf][nf][0], d[mf][nf][1], d[mf][nf][2], d[mf][nf][3],
                             a[mf][0], a[mf][1], a[mf][2], a[mf][3],
                             bl[nf >> 1][(nf & 1)], bl[nf >> 1][(nf & 1) + 2]);
                }
#pragma unroll
            for (int mf = 0; mf < 4; mf++)
                ldmat4(a[mf][0], a[mf][1], a[mf][2], a[mf][3],
                       sAlo + tile_off(wm * 64 + mf * 16 + aRow, cb));
#pragma unroll
            for (int mf = 0; mf < 4; mf++)
#pragma unroll
                for (int nf = 0; nf < 4; nf++)
                    mma16816(d[mf][nf][0], d[mf][nf][1], d[mf][nf][2], d[mf][nf][3],
                             a[mf][0], a[mf][1], a[mf][2], a[mf][3],
                             bh[nf >> 1][(nf & 1)], bh[nf >> 1][(nf & 1) + 2]);
        }
        __syncthreads();
    }

#pragma unroll
    for (int mf = 0; mf < 4; mf++) {
        int row = m0 + wm * 64 + mf * 16 + (lane >> 2);
#pragma unroll
        for (int half = 0; half < 2; half++) {
            int r = row + half * 8;
            if (r >= M) continue;
#pragma unroll
            for (int nf = 0; nf < 4; nf++) {
                int col = n0 + wn * 32 + nf * 8 + (lane & 3) * 2;
                float v0 = d[mf][nf][half * 2], v1 = d[mf][nf][half * 2 + 1];
                if (MODE >= 1) {
                    v0 += __ldg(bias + col);
                    v1 += __ldg(bias + col + 1);
                }
                if (MODE == 1) {
                    v0 = fmaxf(v0, 0.f); v1 = fmaxf(v1, 0.f);
                    __nv_bfloat16 h0, l0, h1, l1;
                    split1(v0, h0, l0); split1(v1, h1, l1);
                    __nv_bfloat162 hh; hh.x = h0; hh.y = h1;
                    __nv_bfloat162 ll; ll.x = l0; ll.y = l1;
                    *(__nv_bfloat162*)(Chi + (size_t)r * N + col) = hh;
                    *(__nv_bfloat162*)(Clo + (size_t)r * N + col) = ll;
                } else {
                    *(float2*)(Cf + (size_t)r * N + col) = make_float2(v0, v1);
                }
            }
        }
    }
}

// ---------------- graph part: sorted aggregation ----------------
__global__ void mask_zero(float* __restrict__ h, const void* __restrict__ idx)
{
    long long r = load_idx(idx, blockIdx.x, g_is64);
    ((float4*)(h + r * HIDDEN))[threadIdx.x] = make_float4(0.f, 0.f, 0.f, 0.f);
}

// zero counters + build Ctab + detect idx dtype, one launch
__global__ void prep_misc(int* __restrict__ deg, int* __restrict__ cnt,
                          const float* __restrict__ E1, const float* __restrict__ E2,
                          float* __restrict__ Ctab, const int* __restrict__ ei_words)
{
    int i = blockIdx.x * 256 + threadIdx.x;
    if (i == 0) {
        int is64 = 1;
        for (int k = 1; k < 64; k += 2)
            if (ei_words[k] != 0) { is64 = 0; break; }
        g_is64 = is64;
    }
    if (i < NNODES) { deg[i] = 0; cnt[i] = 0; }
    if (i < 10 * HIDDEN) {
        int c = i / HIDDEN, dd = i % HIDDEN;
        int r1 = (c == 9) ? 4 : (c % 3);
        int r2 = (c == 9) ? 0 : (c / 3);
        Ctab[i] = E1[r1 * HIDDEN + dd] + E2[r2 * HIDDEN + dd];
    }
}

__global__ void hist_dst(const void* __restrict__ ei, int* __restrict__ deg)
{
    int e = blockIdx.x * 256 + threadIdx.x;
    if (e >= NEDGES) return;
    int dst = (int)load_idx(ei, (long long)NEDGES + e, g_is64);
    atomicAdd(&deg[dst], 1);
}

// Exclusive prefix scan over NNODES ints (= 5000 int4). Single block, 1024 thr.
__global__ __launch_bounds__(1024)
void scan_deg(const int4* __restrict__ deg4, int4* __restrict__ off4)
{
    __shared__ int wsum[32];
    const int t = threadIdx.x, lane = t & 31, w = t >> 5;
    const int base = t * 5;                   // int4 index
    int4 v[5];
    int sum = 0;
#pragma unroll
    for (int i = 0; i < 5; i++) {
        int idx = base + i;
        v[i] = (idx < 5000) ? deg4[idx] : make_int4(0, 0, 0, 0);
        sum += v[i].x + v[i].y + v[i].z + v[i].w;
    }
    int s = sum;
#pragma unroll
    for (int dlt = 1; dlt < 32; dlt <<= 1) {
        int o = __shfl_up_sync(0xffffffff, s, dlt);
        if (lane >= dlt) s += o;
    }
    if (lane == 31) wsum[w] = s;
    __syncthreads();
    if (w == 0) {
        int ws = (t < 32) ? wsum[t] : 0;
#pragma unroll
        for (int dlt = 1; dlt < 32; dlt <<= 1) {
            int o = __shfl_up_sync(0xffffffff, ws, dlt);
            if (lane >= dlt) ws += o;
        }
        if (t < 32) wsum[t] = ws;
    }
    __syncthreads();
    int pre = s - sum + (w > 0 ? wsum[w - 1] : 0);
#pragma unroll
    for (int i = 0; i < 5; i++) {
        int idx = base + i;
        if (idx < 5000) {
            int4 o;
            o.x = pre;            pre += v[i].x;
            o.y = pre;            pre += v[i].y;
            o.z = pre;            pre += v[i].z;
            o.w = pre;            pre += v[i].w;
            off4[idx] = o;
        }
    }
}

__global__ void scatter_edges(const void* __restrict__ ei, const void* __restrict__ ea,
                              const int* __restrict__ off, int* __restrict__ cnt,
                              int2* __restrict__ sorted)
{
    int e = blockIdx.x * 256 + threadIdx.x;
    if (e >= NEDGES) return;
    const int is64 = g_is64;
    int src = (int)load_idx(ei, e, is64);
    int dst = (int)load_idx(ei, (long long)NEDGES + e, is64);
    int a0  = (int)load_idx(ea, 2LL * e, is64);
    int a1  = (int)load_idx(ea, 2LL * e + 1, is64);
    int pos = off[dst] + atomicAdd(&cnt[dst], 1);
    sorted[pos] = make_int2(src, a0 + 3 * a1);
}

// One 64-thread block per node: register accumulation + fused bf16 hi/lo split
__global__ __launch_bounds__(64)
void aggregate(const float* __restrict__ h1, const int2* __restrict__ sorted,
               const int* __restrict__ off, const float* __restrict__ Ctab,
               __nv_bfloat16* __restrict__ aghi, __nv_bfloat16* __restrict__ aglo)
{
    const int n = blockIdx.x;
    const int t = threadIdx.x;
    const int s0 = off[n];
    const int s1 = (n == NNODES - 1) ? NEDGES : off[n + 1];

    float4 acc = ((const float4*)(h1 + (size_t)n * HIDDEN))[t];
    float4 cs  = ((const float4*)(Ctab + 9 * HIDDEN))[t];
    acc.x += cs.x; acc.y += cs.y; acc.z += cs.z; acc.w += cs.w;

    int p = s0;
    for (; p + 1 < s1; p += 2) {
        int2 r0 = __ldg(&sorted[p]);
        int2 r1 = __ldg(&sorted[p + 1]);
        float4 x0 = ((const float4*)(h1 + (size_t)r0.x * HIDDEN))[t];
        float4 c0 = ((const float4*)(Ctab + r0.y * HIDDEN))[t];
        float4 x1 = ((const float4*)(h1 + (size_t)r1.x * HIDDEN))[t];
        float4 c1 = ((const float4*)(Ctab + r1.y * HIDDEN))[t];
        acc.x += x0.x + c0.x; acc.y += x0.y + c0.y;
        acc.z += x0.z + c0.z; acc.w += x0.w + c0.w;
        acc.x += x1.x + c1.x; acc.y += x1.y + c1.y;
        acc.z += x1.z + c1.z; acc.w += x1.w + c1.w;
    }
    if (p < s1) {
        int2 rec = __ldg(&sorted[p]);
        float4 xv = ((const float4*)(h1 + (size_t)rec.x * HIDDEN))[t];
        float4 cv = ((const float4*)(Ctab + rec.y * HIDDEN))[t];
        acc.x += xv.x + cv.x; acc.y += xv.y + cv.y;
        acc.z += xv.z + cv.z; acc.w += xv.w + cv.w;
    }

    __nv_bfloat16 h[4], l[4];
    split1(acc.x, h[0], l[0]); split1(acc.y, h[1], l[1]);
    split1(acc.z, h[2], l[2]); split1(acc.w, h[3], l[3]);
    ((uint2*)(aghi + (size_t)n * HIDDEN))[t] = *(uint2*)h;
    ((uint2*)(aglo + (size_t)n * HIDDEN))[t] = *(uint2*)l;
}

extern "C" void kernel_launch(void* const* d_in, const int* in_sizes, int n_in,
                              void* d_out, int out_size)
{
    const float* x     = (const float*)d_in[0];
    const void*  ei    = d_in[1];
    const void*  ea    = d_in[2];
    const void*  mask  = d_in[3];
    const float* pa    = (const float*)d_in[4];
    const float* W_enc = (const float*)d_in[5];
    const float* E1    = (const float*)d_in[6];
    const float* E2    = (const float*)d_in[7];
    const float* W1    = (const float*)d_in[8];
    const float* b1    = (const float*)d_in[9];
    const float* W2    = (const float*)d_in[10];
    const float* b2    = (const float*)d_in[11];
    float* out = (float*)d_out;

    float *h1, *Ctab;
    int *deg, *cnt, *off;
    int2 *sorted;
    __nv_bfloat16 *xhi, *xlo, *aghi, *aglo, *h2hi, *h2lo;
    __nv_bfloat16 *Wehi, *Welo, *W1hi, *W1lo, *W2hi, *W2lo;
    cudaGetSymbolAddress((void**)&h1,     g_h1);
    cudaGetSymbolAddress((void**)&Ctab,   g_Ctab);
    cudaGetSymbolAddress((void**)&deg,    g_deg);
    cudaGetSymbolAddress((void**)&cnt,    g_cnt);
    cudaGetSymbolAddress((void**)&off,    g_off);
    cudaGetSymbolAddress((void**)&sorted, g_sorted);
    cudaGetSymbolAddress((void**)&xhi,  g_x_hi);
    cudaGetSymbolAddress((void**)&xlo,  g_x_lo);
    cudaGetSymbolAddress((void**)&aghi, g_ag_hi);
    cudaGetSymbolAddress((void**)&aglo, g_ag_lo);
    cudaGetSymbolAddress((void**)&h2hi, g_h2_hi);
    cudaGetSymbolAddress((void**)&h2lo, g_h2_lo);
    cudaGetSymbolAddress((void**)&Wehi, g_We_hi);
    cudaGetSymbolAddress((void**)&Welo, g_We_lo);
    cudaGetSymbolAddress((void**)&W1hi, g_W1_hi);
    cudaGetSymbolAddress((void**)&W1lo, g_W1_lo);
    cudaGetSymbolAddress((void**)&W2hi, g_W2_hi);
    cudaGetSymbolAddress((void**)&W2lo, g_W2_lo);

    const int SMEM_SZ = 2 * STG_B;   // 65536
    cudaFuncSetAttribute(gemm_mma<0>, cudaFuncAttributeMaxDynamicSharedMemorySize, SMEM_SZ);
    cudaFuncSetAttribute(gemm_mma<1>, cudaFuncAttributeMaxDynamicSharedMemorySize, SMEM_SZ);
    cudaFuncSetAttribute(gemm_mma<2>, cudaFuncAttributeMaxDynamicSharedMemorySize, SMEM_SZ);

    const int MB = (NNODES + 127) / 128;   // 157
    const int EB = (NEDGES + 255) / 256;   // 1250

    // ---- fork: graph-prep chain on side stream ----
    cudaEventRecord(g_evFork, 0);
    cudaStreamWaitEvent(g_s2, g_evFork, 0);
    prep_misc<<<(NNODES + 255) / 256, 256, 0, g_s2>>>(deg, cnt, E1, E2, Ctab, (const int*)ei);
    hist_dst<<<EB, 256, 0, g_s2>>>(ei, deg);
    scan_deg<<<1, 1024, 0, g_s2>>>((const int4*)deg, (int4*)off);
    scatter_edges<<<EB, 256, 0, g_s2>>>(ei, ea, off, cnt, sorted);
    cudaEventRecord(g_evJoin, g_s2);

    // ---- main stream: splits + GEMM1 (independent of graph prep) ----
    split_f32<1><<<(NNODES * HIDDEN / 4 + 255) / 256, 256>>>(x, xhi, xlo, NNODES * HIDDEN / 4, pa);
    split_weights<<<(81920 + 255) / 256, 256>>>(W_enc, W1, W2,
                                                Wehi, Welo, W1hi, W1lo, W2hi, W2lo);
    gemm_mma<0><<<dim3(HIDDEN / 128, MB), 256, SMEM_SZ>>>(
        xhi, xlo, Wehi, Welo, nullptr, h1, nullptr, nullptr, NNODES, HIDDEN, HIDDEN);

    // ---- join, then mask (needs g_is64) + aggregation + GIN MLP ----
    cudaStreamWaitEvent(0, g_evJoin, 0);
    mask_zero<<<2000, 64>>>(h1, mask);
    aggregate<<<NNODES, 64>>>(h1, sorted, off, Ctab, aghi, aglo);

    gemm_mma<1><<<dim3(2 * HIDDEN / 128, MB), 256, SMEM_SZ>>>(
        aghi, aglo, W1hi, W1lo, b1, nullptr, h2hi, h2lo, NNODES, 2 * HIDDEN, HIDDEN);

    gemm_mma<2><<<dim3(HIDDEN / 128, MB), 256, SMEM_SZ>>>(
        h2hi, h2lo, W2hi, W2lo, b2, out, nullptr, nullptr, NNODES, HIDDEN, 2 * HIDDEN);
}